// round 2
// baseline (speedup 1.0000x reference)
#include <cuda_runtime.h>
#include <math.h>

// ---------------------------------------------------------------------------
// SupervisedMoEPredictor: B=8192, M=6, D=128, E=5, K=2, T=60
// N = B*M = 49152 tokens.
//
// Output layout (float32, concatenated in reference return order):
//   final_traj   [N,120]        @ 0
//   final_score  [N]            @ 5898240
//   router_logits[N,5]          @ 5947392
//   topk_idx     [N,2] (floats) @ 6193152
//   aux_loss     [1]            @ 6291456
//   traj_all     [5,N,120]      @ 6291457
//   score_all    [5,N]          @ 35782657
// ---------------------------------------------------------------------------

#define N_TOK 49152

#define OFF_FINAL_TRAJ  0
#define OFF_FINAL_SCORE 5898240
#define OFF_LOGITS      5947392
#define OFF_TOPK        6193152
#define OFF_AUX         6291456
#define OFF_TRAJ_ALL    6291457
#define OFF_SCORE_ALL   35782657

// Scratch (static device globals: allowed; no allocations anywhere)
__device__ float g_bufA[N_TOK * 256];
__device__ float g_bufB[N_TOK * 256];
__device__ float g_part[192 * 5];

__device__ __forceinline__ float gelu_exact(float x) {
    // jax.nn.gelu(approximate=False) = x * 0.5 * (1 + erf(x/sqrt(2)))
    return 0.5f * x * (1.0f + erff(x * 0.70710678118654752440f));
}

// ---------------------------------------------------------------------------
// Generic fp32 GEMM with fused bias + optional exact GELU.
//   C[N_TOK, Nout] = act(A[N_TOK, Kd] @ W[Kd, Nout] + bias)
// Tile: 128(tokens) x 128(cols) x 8(K). 256 threads, 8x8 microtile/thread.
// Requires: Kd % 8 == 0, A rows 16B-aligned (Kd % 4 == 0). Nout arbitrary.
// ---------------------------------------------------------------------------
__global__ __launch_bounds__(256)
void gemm_bias_act(const float* __restrict__ A, const float* __restrict__ W,
                   const float* __restrict__ bias, float* __restrict__ C,
                   int Kd, int Nout, int act) {
    __shared__ float As[8][128];   // A tile, transposed: As[k][m]
    __shared__ float Bs[8][128];   // W tile: Bs[k][n]

    const int bm = blockIdx.y * 128;           // token offset
    const int bn = blockIdx.x * 128;           // output-col offset
    const int tid = threadIdx.x;
    const int tx = tid & 15;                   // 0..15 -> col group
    const int ty = tid >> 4;                   // 0..15 -> row group

    float acc[8][8];
#pragma unroll
    for (int i = 0; i < 8; i++)
#pragma unroll
        for (int j = 0; j < 8; j++) acc[i][j] = 0.0f;

    const int ar = tid >> 1;                   // 0..127 (A tile row)
    const int ac = (tid & 1) * 4;              // 0 or 4 (A tile col)
    const int bk = tid >> 5;                   // 0..7   (B tile k)
    const int bj = (tid & 31) * 4;             // 0..124 (B tile col)

    for (int k0 = 0; k0 < Kd; k0 += 8) {
        // Load A tile (128x8) as float4, store transposed
        {
            const float4 v = *reinterpret_cast<const float4*>(
                &A[(size_t)(bm + ar) * Kd + k0 + ac]);
            As[ac + 0][ar] = v.x;
            As[ac + 1][ar] = v.y;
            As[ac + 2][ar] = v.z;
            As[ac + 3][ar] = v.w;
        }
        // Load W tile (8x128), guarded on Nout
        {
            const size_t wrow = (size_t)(k0 + bk) * Nout;
#pragma unroll
            for (int u = 0; u < 4; u++) {
                const int col = bn + bj + u;
                Bs[bk][bj + u] = (col < Nout) ? W[wrow + col] : 0.0f;
            }
        }
        __syncthreads();

#pragma unroll
        for (int kk = 0; kk < 8; kk++) {
            float a[8], b[8];
#pragma unroll
            for (int i = 0; i < 8; i++) a[i] = As[kk][ty * 8 + i];
#pragma unroll
            for (int j = 0; j < 8; j++) b[j] = Bs[kk][tx * 8 + j];
#pragma unroll
            for (int i = 0; i < 8; i++)
#pragma unroll
                for (int j = 0; j < 8; j++)
                    acc[i][j] = fmaf(a[i], b[j], acc[i][j]);
        }
        __syncthreads();
    }

    // Epilogue: bias + activation + guarded store
#pragma unroll
    for (int j = 0; j < 8; j++) {
        const int col = bn + tx * 8 + j;
        if (col >= Nout) continue;
        const float bv = bias[col];
#pragma unroll
        for (int i = 0; i < 8; i++) {
            const int row = bm + ty * 8 + i;
            float v = acc[i][j] + bv;
            if (act) v = gelu_exact(v);
            C[(size_t)row * Nout + col] = v;
        }
    }
}

// ---------------------------------------------------------------------------
// Aux-loss: deterministic two-pass reduction of mean softmax probs.
// ---------------------------------------------------------------------------
__global__ void aux_accum(const float* __restrict__ logits, float* __restrict__ part) {
    __shared__ float red[256];
    const int tok = blockIdx.x * 256 + threadIdx.x;   // 192*256 == N_TOK exactly
    float l[5];
#pragma unroll
    for (int e = 0; e < 5; e++) l[e] = logits[(size_t)tok * 5 + e];
    float mx = l[0];
#pragma unroll
    for (int e = 1; e < 5; e++) mx = fmaxf(mx, l[e]);
    float p[5], s = 0.0f;
#pragma unroll
    for (int e = 0; e < 5; e++) { p[e] = expf(l[e] - mx); s += p[e]; }
    const float inv = 1.0f / s;
#pragma unroll
    for (int e = 0; e < 5; e++) {
        red[threadIdx.x] = p[e] * inv;
        __syncthreads();
        for (int off = 128; off > 0; off >>= 1) {
            if (threadIdx.x < off) red[threadIdx.x] += red[threadIdx.x + off];
            __syncthreads();
        }
        if (threadIdx.x == 0) part[blockIdx.x * 5 + e] = red[0];
        __syncthreads();
    }
}

__global__ void aux_final(const float* __restrict__ part, float* __restrict__ aux) {
    float s[5] = {0, 0, 0, 0, 0};
    for (int b = 0; b < 192; b++)
#pragma unroll
        for (int e = 0; e < 5; e++) s[e] += part[b * 5 + e];
    float ent = 0.0f, l2 = 0.0f;
#pragma unroll
    for (int e = 0; e < 5; e++) {
        const float a = s[e] / (float)N_TOK;
        ent -= a * logf(a + 1e-8f);
        l2 += (a - 0.2f) * (a - 0.2f);
    }
    l2 *= 0.2f;  // mean over 5 experts
    aux[0] = -ent * 0.01f + 0.01f * l2;
}

// ---------------------------------------------------------------------------
// Finalize: per-token top-2 (lowest-index tie-break, matching jax top_k),
// softmax of the 2 selected logits, gather + 0.3/0.7 blend (in place over
// the shared-head results already stored in final_traj/final_score).
// One warp per token; 4 tokens per 128-thread block.
// ---------------------------------------------------------------------------
__global__ void finalize_kernel(const float* __restrict__ logits,
                                float* __restrict__ final_traj,
                                float* __restrict__ final_score,
                                float* __restrict__ topk_out,
                                const float* __restrict__ traj_all,
                                const float* __restrict__ score_all) {
    const int tok = blockIdx.x * 4 + (threadIdx.x >> 5);
    const int lane = threadIdx.x & 31;
    if (tok >= N_TOK) return;

    float l[5];
#pragma unroll
    for (int e = 0; e < 5; e++) l[e] = logits[(size_t)tok * 5 + e];

    int i0 = 0; float v0 = l[0];
#pragma unroll
    for (int e = 1; e < 5; e++)
        if (l[e] > v0) { v0 = l[e]; i0 = e; }
    int i1 = -1; float v1 = -3.4e38f;
#pragma unroll
    for (int e = 0; e < 5; e++)
        if (e != i0 && l[e] > v1) { v1 = l[e]; i1 = e; }

    // softmax over [v0, v1], v0 >= v1
    const float e1 = expf(v1 - v0);
    const float inv = 1.0f / (1.0f + e1);
    const float p0 = inv, p1 = e1 * inv;

    if (lane == 0) {
        topk_out[(size_t)tok * 2 + 0] = (float)i0;
        topk_out[(size_t)tok * 2 + 1] = (float)i1;
        const float sh = final_score[tok];
        const float uns = p0 * score_all[(size_t)i0 * N_TOK + tok]
                        + p1 * score_all[(size_t)i1 * N_TOK + tok];
        final_score[tok] = 0.3f * sh + 0.7f * uns;
    }

    const float* t0 = traj_all + (size_t)i0 * N_TOK * 120 + (size_t)tok * 120;
    const float* t1 = traj_all + (size_t)i1 * N_TOK * 120 + (size_t)tok * 120;
    float* ft = final_traj + (size_t)tok * 120;
    for (int t = lane; t < 120; t += 32) {
        const float uns = p0 * t0[t] + p1 * t1[t];
        ft[t] = 0.3f * ft[t] + 0.7f * uns;
    }
}

// ---------------------------------------------------------------------------
// Host launcher (graph-capturable: kernel launches only)
// ---------------------------------------------------------------------------
extern "C" void kernel_launch(void* const* d_in, const int* in_sizes, int n_in,
                              void* d_out, int out_size) {
    (void)in_sizes; (void)n_in; (void)out_size;

    float* bufA; float* bufB; float* part;
    cudaGetSymbolAddress((void**)&bufA, g_bufA);
    cudaGetSymbolAddress((void**)&bufB, g_bufB);
    cudaGetSymbolAddress((void**)&part, g_part);

    const float* in[31];
    for (int i = 0; i < 31; i++) in[i] = (const float*)d_in[i];
    float* out = (float*)d_out;

    float* final_traj  = out + OFF_FINAL_TRAJ;
    float* final_score = out + OFF_FINAL_SCORE;
    float* logits      = out + OFF_LOGITS;
    float* topk        = out + OFF_TOPK;
    float* aux         = out + OFF_AUX;
    float* traj_all    = out + OFF_TRAJ_ALL;
    float* score_all   = out + OFF_SCORE_ALL;

    const dim3 thr(256);
    auto G = [&](const float* A, const float* W, const float* B, float* C,
                 int Kd, int Nout, int act) {
        dim3 grid((Nout + 127) / 128, N_TOK / 128);
        gemm_bias_act<<<grid, thr>>>(A, W, B, C, Kd, Nout, act);
    };

    const float* X = in[0];

    // Router: 128 -> 256 -> 128 -> 5
    G(X,    in[1], in[2], bufA,   128, 256, 1);
    G(bufA, in[3], in[4], bufB,   256, 128, 1);
    G(bufB, in[5], in[6], logits, 128,   5, 0);

    // Aux loss (needs logits)
    aux_accum<<<192, 256>>>(logits, part);
    aux_final<<<1, 1>>>(part, aux);

    // Shared traj head: 128 -> 256 -> 256 -> 120  (raw result into final_traj slot)
    G(X,    in[7],  in[8],  bufA,       128, 256, 1);
    G(bufA, in[9],  in[10], bufB,       256, 256, 1);
    G(bufB, in[11], in[12], final_traj, 256, 120, 0);

    // Shared score head: 128 -> 128 -> 64 -> 1  (raw result into final_score slot)
    G(X,    in[13], in[14], bufA,        128, 128, 1);
    G(bufA, in[15], in[16], bufB,        128,  64, 1);
    G(bufB, in[17], in[18], final_score,  64,   1, 0);

    // Expert traj stacks (dense over all 5 experts) -> traj_all
    for (int e = 0; e < 5; e++) {
        G(X,    in[19] + (size_t)e * 128 * 256, in[20] + (size_t)e * 256, bufA, 128, 256, 1);
        G(bufA, in[21] + (size_t)e * 256 * 256, in[22] + (size_t)e * 256, bufB, 256, 256, 1);
        G(bufB, in[23] + (size_t)e * 256 * 120, in[24] + (size_t)e * 120,
          traj_all + (size_t)e * N_TOK * 120, 256, 120, 0);
    }

    // Expert score stacks -> score_all
    for (int e = 0; e < 5; e++) {
        G(X,    in[25] + (size_t)e * 128 * 128, in[26] + (size_t)e * 128, bufA, 128, 128, 1);
        G(bufA, in[27] + (size_t)e * 128 * 64,  in[28] + (size_t)e * 64,  bufB, 128,  64, 1);
        G(bufB, in[29] + (size_t)e * 64,        in[30] + (size_t)e,
          score_all + (size_t)e * N_TOK, 64, 1, 0);
    }

    // Top-2 combine + blend
    finalize_kernel<<<N_TOK / 4, 128>>>(logits, final_traj, final_score, topk,
                                        traj_all, score_all);
}

// round 4
// speedup vs baseline: 1.6080x; 1.6080x over previous
#include <cuda_runtime.h>
#include <cuda_bf16.h>
#include <cstdint>
#include <math.h>

// ---------------------------------------------------------------------------
// SupervisedMoEPredictor: B=8192, M=6, D=128, E=5, K=2, T=60
// N = B*M = 49152 tokens.
//
// Output layout (float32, concatenated in reference return order):
//   final_traj   [N,120]        @ 0
//   final_score  [N]            @ 5898240
//   router_logits[N,5]          @ 5947392
//   topk_idx     [N,2] (floats) @ 6193152
//   aux_loss     [1]            @ 6291456
//   traj_all     [5,N,120]      @ 6291457
//   score_all    [5,N]          @ 35782657
//
// Strategy: all Nout>=64 GEMMs on tensor cores (mma.sync bf16) with a 3-term
// hi/lo split (xh*wh + xh*wl + xl*wh) giving ~1e-5 relative accuracy.
// Intermediates live as bf16 hi/lo planes. Tiny heads (Nout=5 / Nout=1) use
// warp-per-token dot kernels.
// ---------------------------------------------------------------------------

#define N_TOK 49152

#define OFF_FINAL_TRAJ  0
#define OFF_FINAL_SCORE 5898240
#define OFF_LOGITS      5947392
#define OFF_TOPK        6193152
#define OFF_AUX         6291456
#define OFF_TRAJ_ALL    6291457
#define OFF_SCORE_ALL   35782657

// Weight hi/lo arena offsets (elements)
#define WOFF_RW1    0
#define WOFF_RW2    32768
#define WOFF_SHTW1  65536
#define WOFF_SHTW2  98304
#define WOFF_SHTW3  163840
#define WOFF_SHSW1  194560
#define WOFF_SHSW2  210944
#define WOFF_EXTW1  219136
#define WOFF_EXTW2  382976
#define WOFF_EXTW3  710656
#define WOFF_EXSW1  864256
#define WOFF_EXSW2  946176
#define W_ARENA_SZ  987136

// ---------------- scratch (device globals; no allocations) -----------------
__device__ __nv_bfloat16 g_wh[W_ARENA_SZ];
__device__ __nv_bfloat16 g_wl[W_ARENA_SZ];
__device__ __nv_bfloat16 g_xh[N_TOK * 128];
__device__ __nv_bfloat16 g_xl[N_TOK * 128];
__device__ __nv_bfloat16 g_ah[N_TOK * 256];
__device__ __nv_bfloat16 g_al[N_TOK * 256];
__device__ __nv_bfloat16 g_bh[N_TOK * 256];
__device__ __nv_bfloat16 g_bl[N_TOK * 256];
__device__ float g_part[192 * 5];

__device__ __forceinline__ float gelu_exact(float x) {
    return 0.5f * x * (1.0f + erff(x * 0.70710678118654752440f));
}

// ---------------------------------------------------------------------------
// fp32 -> (hi, lo) bf16 split, vectorized by 4
// ---------------------------------------------------------------------------
__global__ void split_kernel(const float* __restrict__ src,
                             __nv_bfloat16* __restrict__ hi,
                             __nv_bfloat16* __restrict__ lo, int n4) {
    int i = blockIdx.x * blockDim.x + threadIdx.x;
    if (i >= n4) return;
    float4 v = reinterpret_cast<const float4*>(src)[i];
    union { __nv_bfloat16 b[4]; uint2 u; } H, L;
    float vv[4] = {v.x, v.y, v.z, v.w};
#pragma unroll
    for (int u = 0; u < 4; u++) {
        __nv_bfloat16 h = __float2bfloat16(vv[u]);
        H.b[u] = h;
        L.b[u] = __float2bfloat16(vv[u] - __bfloat162float(h));
    }
    reinterpret_cast<uint2*>(hi)[i] = H.u;
    reinterpret_cast<uint2*>(lo)[i] = L.u;
}

// ---------------------------------------------------------------------------
// Tensor-core GEMM: C[N_TOK, Nout] = act(A @ W + bias)
// A given as hi/lo bf16 planes [N_TOK, lda(=Kd)], W as hi/lo planes [Kd, Nout].
// 3-term split: Ah*Wh + Ah*Wl + Al*Wh.
// Tile 128x128x32, 8 warps, warp tile 64x32, mma.m16n8k16.
// mode 0: write fp32 to C (no act). mode 1: gelu, write hi/lo planes Oh/Ol.
// ---------------------------------------------------------------------------
__global__ __launch_bounds__(256)
void tc_gemm(const __nv_bfloat16* __restrict__ Ah,
             const __nv_bfloat16* __restrict__ Al, int lda,
             const __nv_bfloat16* __restrict__ Wh,
             const __nv_bfloat16* __restrict__ Wl,
             const float* __restrict__ bias, int Kd, int Nout, int mode,
             float* __restrict__ C,
             __nv_bfloat16* __restrict__ Oh, __nv_bfloat16* __restrict__ Ol) {
    __shared__ __nv_bfloat16 As[128 * 40];   // [m][k], row stride 40 elems
    __shared__ __nv_bfloat16 Ws[32 * 136];   // [k][n], row stride 136 elems

    const int tid = threadIdx.x;
    const int lane = tid & 31;
    const int wid = tid >> 5;
    const int bm = blockIdx.y * 128;
    const int bn = blockIdx.x * 128;
    const int wm = (wid >> 2) * 64;
    const int wn = (wid & 3) * 32;

    float acc[4][4][4];
#pragma unroll
    for (int mi = 0; mi < 4; mi++)
#pragma unroll
        for (int nj = 0; nj < 4; nj++)
#pragma unroll
            for (int u = 0; u < 4; u++) acc[mi][nj][u] = 0.0f;

    const __nv_bfloat16* APl[3] = {Ah, Ah, Al};
    const __nv_bfloat16* WPl[3] = {Wh, Wl, Wh};

    const unsigned sA = (unsigned)__cvta_generic_to_shared(As);
    const unsigned sW = (unsigned)__cvta_generic_to_shared(Ws);

    for (int ch = 0; ch < 3; ch++) {
        const __nv_bfloat16* Ap = APl[ch];
        const __nv_bfloat16* Wp = WPl[ch];
        for (int k0 = 0; k0 < Kd; k0 += 32) {
            // ---- stage A tile (128 x 32) ----
#pragma unroll
            for (int t = 0; t < 2; t++) {
                int li = tid + t * 256;
                int r = li >> 2, q = li & 3;
                uint4 v = *reinterpret_cast<const uint4*>(
                    Ap + (size_t)(bm + r) * lda + k0 + q * 8);
                *reinterpret_cast<uint4*>(As + r * 40 + q * 8) = v;
            }
            // ---- stage W tile (32 x 128), guard col < Nout ----
#pragma unroll
            for (int t = 0; t < 2; t++) {
                int li = tid + t * 256;
                int r = li >> 4, q = li & 15;
                int col = bn + q * 8;
                const __nv_bfloat16* wrow = Wp + (size_t)(k0 + r) * Nout;
                uint4 v;
                if (col + 8 <= Nout) {
                    v = *reinterpret_cast<const uint4*>(wrow + col);
                } else {
                    union { __nv_bfloat16 b[8]; uint4 u; } tmp;
#pragma unroll
                    for (int u = 0; u < 8; u++)
                        tmp.b[u] = (col + u < Nout) ? wrow[col + u]
                                                    : __float2bfloat16(0.0f);
                    v = tmp.u;
                }
                *reinterpret_cast<uint4*>(Ws + r * 136 + q * 8) = v;
            }
            __syncthreads();

#pragma unroll
            for (int kk = 0; kk < 32; kk += 16) {
                unsigned a0[4], a1[4], a2[4], a3[4];
#pragma unroll
                for (int mi = 0; mi < 4; mi++) {
                    unsigned addr = sA +
                        ((wm + mi * 16 + (lane & 15)) * 40 + kk + (lane >> 4) * 8) * 2;
                    unsigned r0, r1, r2, r3;
                    asm volatile(
                        "ldmatrix.sync.aligned.m8n8.x4.shared.b16 {%0,%1,%2,%3}, [%4];"
                        : "=r"(r0), "=r"(r1), "=r"(r2), "=r"(r3)
                        : "r"(addr));
                    a0[mi] = r0; a1[mi] = r1; a2[mi] = r2; a3[mi] = r3;
                }
                unsigned b0[4], b1[4];
                {
                    unsigned addr = sW +
                        ((kk + (lane & 15)) * 136 + wn + (lane >> 4) * 8) * 2;
                    unsigned r0, r1, r2, r3;
                    asm volatile(
                        "ldmatrix.sync.aligned.m8n8.x4.trans.shared.b16 {%0,%1,%2,%3}, [%4];"
                        : "=r"(r0), "=r"(r1), "=r"(r2), "=r"(r3)
                        : "r"(addr));
                    b0[0] = r0; b1[0] = r1; b0[1] = r2; b1[1] = r3;
                }
                {
                    unsigned addr = sW +
                        ((kk + (lane & 15)) * 136 + wn + 16 + (lane >> 4) * 8) * 2;
                    unsigned r0, r1, r2, r3;
                    asm volatile(
                        "ldmatrix.sync.aligned.m8n8.x4.trans.shared.b16 {%0,%1,%2,%3}, [%4];"
                        : "=r"(r0), "=r"(r1), "=r"(r2), "=r"(r3)
                        : "r"(addr));
                    b0[2] = r0; b1[2] = r1; b0[3] = r2; b1[3] = r3;
                }
#pragma unroll
                for (int mi = 0; mi < 4; mi++)
#pragma unroll
                    for (int nj = 0; nj < 4; nj++) {
                        asm volatile(
                            "mma.sync.aligned.m16n8k16.row.col.f32.bf16.bf16.f32 "
                            "{%0,%1,%2,%3}, {%4,%5,%6,%7}, {%8,%9}, {%0,%1,%2,%3};"
                            : "+f"(acc[mi][nj][0]), "+f"(acc[mi][nj][1]),
                              "+f"(acc[mi][nj][2]), "+f"(acc[mi][nj][3])
                            : "r"(a0[mi]), "r"(a1[mi]), "r"(a2[mi]), "r"(a3[mi]),
                              "r"(b0[nj]), "r"(b1[nj]));
                    }
            }
            __syncthreads();
        }
    }

    // ---- epilogue ----
#pragma unroll
    for (int mi = 0; mi < 4; mi++) {
#pragma unroll
        for (int nj = 0; nj < 4; nj++) {
            const int row0 = bm + wm + mi * 16 + (lane >> 2);
            const int col0 = bn + wn + nj * 8 + (lane & 3) * 2;
#pragma unroll
            for (int h = 0; h < 2; h++) {
                const int r = row0 + h * 8;
#pragma unroll
                for (int u = 0; u < 2; u++) {
                    const int c = col0 + u;
                    if (c >= Nout) continue;
                    float v = acc[mi][nj][h * 2 + u] + bias[c];
                    if (mode == 0) {
                        C[(size_t)r * Nout + c] = v;
                    } else {
                        v = gelu_exact(v);
                        __nv_bfloat16 hh = __float2bfloat16(v);
                        Oh[(size_t)r * Nout + c] = hh;
                        Ol[(size_t)r * Nout + c] =
                            __float2bfloat16(v - __bfloat162float(hh));
                    }
                }
            }
        }
    }
}

// ---------------------------------------------------------------------------
// Router final layer: logits[N,5] = (hi+lo)[N,128] @ W[128,5] + b[5]
// Warp per token.
// ---------------------------------------------------------------------------
__global__ __launch_bounds__(256)
void router_final(const __nv_bfloat16* __restrict__ hh,
                  const __nv_bfloat16* __restrict__ ll,
                  const float* __restrict__ W, const float* __restrict__ b,
                  float* __restrict__ logits) {
    __shared__ float ws[640];
    const int tid = threadIdx.x;
    for (int i = tid; i < 640; i += 256) ws[i] = W[i];
    __syncthreads();
    const int lane = tid & 31;
    const int tok = blockIdx.x * 8 + (tid >> 5);

    const size_t base = (size_t)tok * 128 + lane * 4;
    union { uint2 u; __nv_bfloat16 b[4]; } vh, vl;
    vh.u = *reinterpret_cast<const uint2*>(hh + base);
    vl.u = *reinterpret_cast<const uint2*>(ll + base);

    float p[5] = {0, 0, 0, 0, 0};
#pragma unroll
    for (int k = 0; k < 4; k++) {
        const float x = __bfloat162float(vh.b[k]) + __bfloat162float(vl.b[k]);
        const int kk = lane * 4 + k;
#pragma unroll
        for (int e = 0; e < 5; e++) p[e] = fmaf(x, ws[kk * 5 + e], p[e]);
    }
#pragma unroll
    for (int off = 16; off > 0; off >>= 1)
#pragma unroll
        for (int e = 0; e < 5; e++)
            p[e] += __shfl_down_sync(0xffffffffu, p[e], off);
    if (lane == 0) {
#pragma unroll
        for (int e = 0; e < 5; e++) logits[(size_t)tok * 5 + e] = p[e] + b[e];
    }
}

// ---------------------------------------------------------------------------
// Score final layer: out[N] = (hi+lo)[N,64] @ W[64] + b. Warp per token.
// ---------------------------------------------------------------------------
__global__ __launch_bounds__(256)
void score_final(const __nv_bfloat16* __restrict__ hh,
                 const __nv_bfloat16* __restrict__ ll,
                 const float* __restrict__ W, const float* __restrict__ b,
                 float* __restrict__ out) {
    const int tid = threadIdx.x;
    const int lane = tid & 31;
    const int tok = blockIdx.x * 8 + (tid >> 5);
    const size_t base = (size_t)tok * 64 + lane * 2;
    union { unsigned u; __nv_bfloat16 b[2]; } vh, vl;
    vh.u = *reinterpret_cast<const unsigned*>(hh + base);
    vl.u = *reinterpret_cast<const unsigned*>(ll + base);
    float p = (__bfloat162float(vh.b[0]) + __bfloat162float(vl.b[0])) * W[lane * 2]
            + (__bfloat162float(vh.b[1]) + __bfloat162float(vl.b[1])) * W[lane * 2 + 1];
#pragma unroll
    for (int off = 16; off > 0; off >>= 1)
        p += __shfl_down_sync(0xffffffffu, p, off);
    if (lane == 0) out[tok] = p + b[0];
}

// ---------------------------------------------------------------------------
// Aux-loss: deterministic two-pass reduction of mean softmax probs.
// ---------------------------------------------------------------------------
__global__ void aux_accum(const float* __restrict__ logits, float* __restrict__ part) {
    __shared__ float red[256];
    const int tok = blockIdx.x * 256 + threadIdx.x;
    float l[5];
#pragma unroll
    for (int e = 0; e < 5; e++) l[e] = logits[(size_t)tok * 5 + e];
    float mx = l[0];
#pragma unroll
    for (int e = 1; e < 5; e++) mx = fmaxf(mx, l[e]);
    float p[5], s = 0.0f;
#pragma unroll
    for (int e = 0; e < 5; e++) { p[e] = expf(l[e] - mx); s += p[e]; }
    const float inv = 1.0f / s;
#pragma unroll
    for (int e = 0; e < 5; e++) {
        red[threadIdx.x] = p[e] * inv;
        __syncthreads();
        for (int off = 128; off > 0; off >>= 1) {
            if (threadIdx.x < off) red[threadIdx.x] += red[threadIdx.x + off];
            __syncthreads();
        }
        if (threadIdx.x == 0) part[blockIdx.x * 5 + e] = red[0];
        __syncthreads();
    }
}

__global__ void aux_final(const float* __restrict__ part, float* __restrict__ aux) {
    float s[5] = {0, 0, 0, 0, 0};
    for (int b = 0; b < 192; b++)
#pragma unroll
        for (int e = 0; e < 5; e++) s[e] += part[b * 5 + e];
    float ent = 0.0f, l2 = 0.0f;
#pragma unroll
    for (int e = 0; e < 5; e++) {
        const float a = s[e] / (float)N_TOK;
        ent -= a * logf(a + 1e-8f);
        l2 += (a - 0.2f) * (a - 0.2f);
    }
    l2 *= 0.2f;
    aux[0] = -ent * 0.01f + 0.01f * l2;
}

// ---------------------------------------------------------------------------
// Finalize: top-2 (lowest-index tie-break), softmax-of-2, gather + blend.
// ---------------------------------------------------------------------------
__global__ void finalize_kernel(const float* __restrict__ logits,
                                float* __restrict__ final_traj,
                                float* __restrict__ final_score,
                                float* __restrict__ topk_out,
                                const float* __restrict__ traj_all,
                                const float* __restrict__ score_all) {
    const int tok = blockIdx.x * 4 + (threadIdx.x >> 5);
    const int lane = threadIdx.x & 31;
    if (tok >= N_TOK) return;

    float l[5];
#pragma unroll
    for (int e = 0; e < 5; e++) l[e] = logits[(size_t)tok * 5 + e];

    int i0 = 0; float v0 = l[0];
#pragma unroll
    for (int e = 1; e < 5; e++)
        if (l[e] > v0) { v0 = l[e]; i0 = e; }
    int i1 = -1; float v1 = -3.4e38f;
#pragma unroll
    for (int e = 0; e < 5; e++)
        if (e != i0 && l[e] > v1) { v1 = l[e]; i1 = e; }

    const float e1 = expf(v1 - v0);
    const float inv = 1.0f / (1.0f + e1);
    const float p0 = inv, p1 = e1 * inv;

    if (lane == 0) {
        topk_out[(size_t)tok * 2 + 0] = (float)i0;
        topk_out[(size_t)tok * 2 + 1] = (float)i1;
        const float sh = final_score[tok];
        const float uns = p0 * score_all[(size_t)i0 * N_TOK + tok]
                        + p1 * score_all[(size_t)i1 * N_TOK + tok];
        final_score[tok] = 0.3f * sh + 0.7f * uns;
    }

    const float* t0 = traj_all + (size_t)i0 * N_TOK * 120 + (size_t)tok * 120;
    const float* t1 = traj_all + (size_t)i1 * N_TOK * 120 + (size_t)tok * 120;
    float* ft = final_traj + (size_t)tok * 120;
    for (int t = lane; t < 120; t += 32) {
        const float uns = p0 * t0[t] + p1 * t1[t];
        ft[t] = 0.3f * ft[t] + 0.7f * uns;
    }
}

// ---------------------------------------------------------------------------
// Host launcher (graph-capturable: kernel launches only)
// ---------------------------------------------------------------------------
extern "C" void kernel_launch(void* const* d_in, const int* in_sizes, int n_in,
                              void* d_out, int out_size) {
    (void)in_sizes; (void)n_in; (void)out_size;

    __nv_bfloat16 *wh, *wl, *xh, *xl, *ah, *al, *bh, *bl;
    float* part;
    cudaGetSymbolAddress((void**)&wh, g_wh);
    cudaGetSymbolAddress((void**)&wl, g_wl);
    cudaGetSymbolAddress((void**)&xh, g_xh);
    cudaGetSymbolAddress((void**)&xl, g_xl);
    cudaGetSymbolAddress((void**)&ah, g_ah);
    cudaGetSymbolAddress((void**)&al, g_al);
    cudaGetSymbolAddress((void**)&bh, g_bh);
    cudaGetSymbolAddress((void**)&bl, g_bl);
    cudaGetSymbolAddress((void**)&part, g_part);

    const float* in[31];
    for (int i = 0; i < 31; i++) in[i] = (const float*)d_in[i];
    float* out = (float*)d_out;

    float* final_traj  = out + OFF_FINAL_TRAJ;
    float* final_score = out + OFF_FINAL_SCORE;
    float* logits      = out + OFF_LOGITS;
    float* topk        = out + OFF_TOPK;
    float* aux         = out + OFF_AUX;
    float* traj_all    = out + OFF_TRAJ_ALL;
    float* score_all   = out + OFF_SCORE_ALL;

    // ---- split weights + X into hi/lo planes ----
    auto SPLIT = [&](const float* src, int woff, int count) {
        int n4 = count / 4;
        split_kernel<<<(n4 + 255) / 256, 256>>>(src, wh + woff, wl + woff, n4);
    };
    {
        int n4 = (N_TOK * 128) / 4;
        split_kernel<<<(n4 + 255) / 256, 256>>>(in[0], xh, xl, n4);
    }
    SPLIT(in[1],  WOFF_RW1,   32768);
    SPLIT(in[3],  WOFF_RW2,   32768);
    SPLIT(in[7],  WOFF_SHTW1, 32768);
    SPLIT(in[9],  WOFF_SHTW2, 65536);
    SPLIT(in[11], WOFF_SHTW3, 30720);
    SPLIT(in[13], WOFF_SHSW1, 16384);
    SPLIT(in[15], WOFF_SHSW2, 8192);
    SPLIT(in[19], WOFF_EXTW1, 163840);
    SPLIT(in[21], WOFF_EXTW2, 327680);
    SPLIT(in[23], WOFF_EXTW3, 153600);
    SPLIT(in[25], WOFF_EXSW1, 81920);
    SPLIT(in[27], WOFF_EXSW2, 40960);

    // ---- TC GEMM helper ----
    auto G = [&](const __nv_bfloat16* Ah_, const __nv_bfloat16* Al_, int lda,
                 int woff, const float* bias, int Kd, int Nout, int mode,
                 float* C, __nv_bfloat16* Oh_, __nv_bfloat16* Ol_) {
        dim3 grid((Nout + 127) / 128, N_TOK / 128);
        tc_gemm<<<grid, 256>>>(Ah_, Al_, lda, wh + woff, wl + woff,
                               bias, Kd, Nout, mode, C, Oh_, Ol_);
    };

    // Router: 128 -> 256 -> 128 -> 5
    G(xh, xl, 128, WOFF_RW1, in[2], 128, 256, 1, nullptr, ah, al);
    G(ah, al, 256, WOFF_RW2, in[4], 256, 128, 1, nullptr, bh, bl);
    router_final<<<N_TOK / 8, 256>>>(bh, bl, in[5], in[6], logits);
    aux_accum<<<192, 256>>>(logits, part);
    aux_final<<<1, 1>>>(part, aux);

    // Shared traj: 128 -> 256 -> 256 -> 120
    G(xh, xl, 128, WOFF_SHTW1, in[8],  128, 256, 1, nullptr, ah, al);
    G(ah, al, 256, WOFF_SHTW2, in[10], 256, 256, 1, nullptr, bh, bl);
    G(bh, bl, 256, WOFF_SHTW3, in[12], 256, 120, 0, final_traj, nullptr, nullptr);

    // Shared score: 128 -> 128 -> 64 -> 1
    G(xh, xl, 128, WOFF_SHSW1, in[14], 128, 128, 1, nullptr, ah, al);
    G(ah, al, 128, WOFF_SHSW2, in[16], 128, 64, 1, nullptr, bh, bl);
    score_final<<<N_TOK / 8, 256>>>(bh, bl, in[17], in[18], final_score);

    // Expert traj stacks
    for (int e = 0; e < 5; e++) {
        G(xh, xl, 128, WOFF_EXTW1 + e * 32768, in[20] + (size_t)e * 256,
          128, 256, 1, nullptr, ah, al);
        G(ah, al, 256, WOFF_EXTW2 + e * 65536, in[22] + (size_t)e * 256,
          256, 256, 1, nullptr, bh, bl);
        G(bh, bl, 256, WOFF_EXTW3 + e * 30720, in[24] + (size_t)e * 120,
          256, 120, 0, traj_all + (size_t)e * N_TOK * 120, nullptr, nullptr);
    }

    // Expert score stacks
    for (int e = 0; e < 5; e++) {
        G(xh, xl, 128, WOFF_EXSW1 + e * 16384, in[26] + (size_t)e * 128,
          128, 128, 1, nullptr, ah, al);
        G(ah, al, 128, WOFF_EXSW2 + e * 8192, in[28] + (size_t)e * 64,
          128, 64, 1, nullptr, bh, bl);
        score_final<<<N_TOK / 8, 256>>>(bh, bl, in[29] + (size_t)e * 64,
                                        in[30] + e, score_all + (size_t)e * N_TOK);
    }

    // Top-2 combine + blend
    finalize_kernel<<<N_TOK / 4, 128>>>(logits, final_traj, final_score, topk,
                                        traj_all, score_all);
}

// round 7
// speedup vs baseline: 1.8366x; 1.1422x over previous
#include <cuda_runtime.h>
#include <cuda_bf16.h>
#include <cstdint>
#include <math.h>

// ---------------------------------------------------------------------------
// SupervisedMoEPredictor: B=8192, M=6, D=128, E=5, K=2, T=60. N = 49152.
//
// Output layout (float32):
//   final_traj   [N,120]        @ 0
//   final_score  [N]            @ 5898240
//   router_logits[N,5]          @ 5947392
//   topk_idx     [N,2] (floats) @ 6193152
//   aux_loss     [1]            @ 6291456
//   traj_all     [5,N,120]      @ 6291457
//   score_all    [5,N]          @ 35782657
//
// NOTE: harness compiles for plain sm_100 (no 'a' features) -> no tcgen05.
// GEMMs use mma.sync.m16n8k16.bf16 with a 3-term hi/lo split
// (Ah*Wh + Ah*Wl + Al*Wh ~ fp32 accuracy), fused into ONE k-pass per stage,
// with cp.async double-buffered staging.
// ---------------------------------------------------------------------------

#define N_TOK 49152

#define OFF_FINAL_TRAJ  0
#define OFF_FINAL_SCORE 5898240
#define OFF_LOGITS      5947392
#define OFF_TOPK        6193152
#define OFF_AUX         6291456
#define OFF_TRAJ_ALL    6291457
#define OFF_SCORE_ALL   35782657

// Weight hi/lo arena offsets (elements), weights kept [Kd, Nout] row-major
#define WOFF_RW1    0
#define WOFF_RW2    32768
#define WOFF_SHTW1  65536
#define WOFF_SHTW2  98304
#define WOFF_SHTW3  163840
#define WOFF_SHSW1  194560
#define WOFF_SHSW2  210944
#define WOFF_EXTW1  219136
#define WOFF_EXTW2  382976
#define WOFF_EXTW3  710656
#define WOFF_EXSW1  864256
#define WOFF_EXSW2  946176
#define W_ARENA_SZ  987136

__device__ __nv_bfloat16 g_wh[W_ARENA_SZ];
__device__ __nv_bfloat16 g_wl[W_ARENA_SZ];
__device__ __nv_bfloat16 g_xh[N_TOK * 128];
__device__ __nv_bfloat16 g_xl[N_TOK * 128];
__device__ __nv_bfloat16 g_ah[N_TOK * 256];
__device__ __nv_bfloat16 g_al[N_TOK * 256];
__device__ __nv_bfloat16 g_bh[N_TOK * 256];
__device__ __nv_bfloat16 g_bl[N_TOK * 256];
__device__ float g_part[192 * 5];

__device__ __forceinline__ float gelu_exact(float x) {
    return 0.5f * x * (1.0f + erff(x * 0.70710678118654752440f));
}

__device__ __forceinline__ unsigned smem_u32(const void* p) {
    unsigned a;
    asm("{ .reg .u64 t; cvta.to.shared.u64 t, %1; cvt.u32.u64 %0, t; }"
        : "=r"(a) : "l"(p));
    return a;
}

__device__ __forceinline__ void cp16(unsigned dst, const void* src, unsigned sz) {
    asm volatile("cp.async.cg.shared.global [%0], [%1], 16, %2;"
                 :: "r"(dst), "l"(src), "r"(sz));
}
#define CP_COMMIT() asm volatile("cp.async.commit_group;" ::: "memory")
#define CP_WAIT(n)  asm volatile("cp.async.wait_group %0;" :: "n"(n) : "memory")

// SMEM stage layout (bytes). A planes: 128 rows x 32 cols, row stride 40 elems.
// W planes: 32 rows x 128 cols, row stride 136 elems. (Strides verified
// conflict-free for ldmatrix in the R4 passing kernel.)
#define AH_OFF   0
#define AL_OFF   10240
#define WH_OFF   20480
#define WL_OFF   29184
#define STAGE_B  37888
#define SMEM_TOT (2 * STAGE_B)

// ---------------------------------------------------------------------------
// fp32 -> (hi, lo) bf16 split, vectorized by 4
// ---------------------------------------------------------------------------
__global__ void split_kernel(const float* __restrict__ src,
                             __nv_bfloat16* __restrict__ hi,
                             __nv_bfloat16* __restrict__ lo, int n4) {
    int i = blockIdx.x * blockDim.x + threadIdx.x;
    if (i >= n4) return;
    float4 v = reinterpret_cast<const float4*>(src)[i];
    union { __nv_bfloat16 b[4]; uint2 u; } H, L;
    float vv[4] = {v.x, v.y, v.z, v.w};
#pragma unroll
    for (int u = 0; u < 4; u++) {
        __nv_bfloat16 h = __float2bfloat16(vv[u]);
        H.b[u] = h;
        L.b[u] = __float2bfloat16(vv[u] - __bfloat162float(h));
    }
    reinterpret_cast<uint2*>(hi)[i] = H.u;
    reinterpret_cast<uint2*>(lo)[i] = L.u;
}

// ---------------------------------------------------------------------------
// Tensor-core GEMM (mma.sync bf16): C[N_TOK, Nout] = act(A @ W + bias)
// A hi/lo [N_TOK, lda]; W hi/lo [Kd, Nout]. Fused 3-term split per k-stage,
// cp.async double-buffered. Tile 128x128x32, 8 warps, warp tile 64x32.
// mode 0: fp32 -> C (no act). mode 1: gelu -> hi/lo planes Oh/Ol.
// ---------------------------------------------------------------------------
__global__ __launch_bounds__(256)
void tc_gemm(const __nv_bfloat16* __restrict__ Ah,
             const __nv_bfloat16* __restrict__ Al, int lda,
             const __nv_bfloat16* __restrict__ Wh,
             const __nv_bfloat16* __restrict__ Wl,
             const float* __restrict__ bias, int Kd, int Nout, int mode,
             float* __restrict__ C,
             __nv_bfloat16* __restrict__ Oh, __nv_bfloat16* __restrict__ Ol) {
    extern __shared__ char smem[];
    const unsigned sbase = smem_u32(smem);

    const int tid = threadIdx.x;
    const int lane = tid & 31;
    const int wid = tid >> 5;
    const int bm = blockIdx.y * 128;
    const int bn = blockIdx.x * 128;
    const int wm = (wid >> 2) * 64;
    const int wn = (wid & 3) * 32;

    float acc[4][4][4];
#pragma unroll
    for (int mi = 0; mi < 4; mi++)
#pragma unroll
        for (int nj = 0; nj < 4; nj++)
#pragma unroll
            for (int u = 0; u < 4; u++) acc[mi][nj][u] = 0.0f;

    const int S = Kd >> 5;   // k-stages of width 32

    // ---- stage loader: issues cp.async for stage s into buffer s&1 ----
    auto load_stage = [&](int s) {
        const unsigned buf = sbase + (unsigned)((s & 1) * STAGE_B);
        const int k0 = s * 32;
        // A planes: 512 chunks of 16B each (r = row 0..127, q = col-group 0..3)
#pragma unroll
        for (int t = 0; t < 2; t++) {
            const int chunk = tid + t * 256;
            const int r = chunk >> 2, q = chunk & 3;
            const unsigned doff = (unsigned)((r * 40 + q * 8) * 2);
            const size_t g = (size_t)(bm + r) * lda + k0 + q * 8;
            cp16(buf + AH_OFF + doff, Ah + g, 16u);
            cp16(buf + AL_OFF + doff, Al + g, 16u);
        }
        // W planes: 512 chunks (r = k-row 0..31, q = col-group 0..15)
#pragma unroll
        for (int t = 0; t < 2; t++) {
            const int chunk = tid + t * 256;
            const int r = chunk >> 4, q = chunk & 15;
            const int col = bn + q * 8;
            const unsigned ok = (col < Nout) ? 16u : 0u;
            const int csafe = (col < Nout) ? col : 0;
            const unsigned doff = (unsigned)((r * 136 + q * 8) * 2);
            const size_t g = (size_t)(k0 + r) * Nout + csafe;
            cp16(buf + WH_OFF + doff, Wh + g, ok);
            cp16(buf + WL_OFF + doff, Wl + g, ok);
        }
    };

    load_stage(0);
    CP_COMMIT();

    for (int s = 0; s < S; s++) {
        if (s + 1 < S) {
            load_stage(s + 1);
            CP_COMMIT();
            CP_WAIT(1);
        } else {
            CP_WAIT(0);
        }
        __syncthreads();

        const unsigned buf = sbase + (unsigned)((s & 1) * STAGE_B);
#pragma unroll
        for (int kk = 0; kk < 32; kk += 16) {
            unsigned a0[4], a1[4], a2[4], a3[4];
            unsigned h0[4], h1[4], l0[4], l1[4];
            // Ah fragments (4 m-tiles)
#pragma unroll
            for (int mi = 0; mi < 4; mi++) {
                unsigned addr = buf + AH_OFF +
                    (unsigned)(((wm + mi * 16 + (lane & 15)) * 40 + kk + (lane >> 4) * 8) * 2);
                unsigned r0, r1, r2, r3;
                asm volatile("ldmatrix.sync.aligned.m8n8.x4.shared.b16 {%0,%1,%2,%3}, [%4];"
                             : "=r"(r0), "=r"(r1), "=r"(r2), "=r"(r3) : "r"(addr));
                a0[mi] = r0; a1[mi] = r1; a2[mi] = r2; a3[mi] = r3;
            }
            // Wh fragments (4 n-tiles, via 2 trans ldmatrix)
            {
                unsigned addr = buf + WH_OFF +
                    (unsigned)(((kk + (lane & 15)) * 136 + wn + (lane >> 4) * 8) * 2);
                unsigned r0, r1, r2, r3;
                asm volatile("ldmatrix.sync.aligned.m8n8.x4.trans.shared.b16 {%0,%1,%2,%3}, [%4];"
                             : "=r"(r0), "=r"(r1), "=r"(r2), "=r"(r3) : "r"(addr));
                h0[0] = r0; h1[0] = r1; h0[1] = r2; h1[1] = r3;
            }
            {
                unsigned addr = buf + WH_OFF +
                    (unsigned)(((kk + (lane & 15)) * 136 + wn + 16 + (lane >> 4) * 8) * 2);
                unsigned r0, r1, r2, r3;
                asm volatile("ldmatrix.sync.aligned.m8n8.x4.trans.shared.b16 {%0,%1,%2,%3}, [%4];"
                             : "=r"(r0), "=r"(r1), "=r"(r2), "=r"(r3) : "r"(addr));
                h0[2] = r0; h1[2] = r1; h0[3] = r2; h1[3] = r3;
            }
            // Wl fragments
            {
                unsigned addr = buf + WL_OFF +
                    (unsigned)(((kk + (lane & 15)) * 136 + wn + (lane >> 4) * 8) * 2);
                unsigned r0, r1, r2, r3;
                asm volatile("ldmatrix.sync.aligned.m8n8.x4.trans.shared.b16 {%0,%1,%2,%3}, [%4];"
                             : "=r"(r0), "=r"(r1), "=r"(r2), "=r"(r3) : "r"(addr));
                l0[0] = r0; l1[0] = r1; l0[1] = r2; l1[1] = r3;
            }
            {
                unsigned addr = buf + WL_OFF +
                    (unsigned)(((kk + (lane & 15)) * 136 + wn + 16 + (lane >> 4) * 8) * 2);
                unsigned r0, r1, r2, r3;
                asm volatile("ldmatrix.sync.aligned.m8n8.x4.trans.shared.b16 {%0,%1,%2,%3}, [%4];"
                             : "=r"(r0), "=r"(r1), "=r"(r2), "=r"(r3) : "r"(addr));
                l0[2] = r0; l1[2] = r1; l0[3] = r2; l1[3] = r3;
            }
#pragma unroll
            for (int mi = 0; mi < 4; mi++)
#pragma unroll
                for (int nj = 0; nj < 4; nj++) {
                    asm volatile(
                        "mma.sync.aligned.m16n8k16.row.col.f32.bf16.bf16.f32 "
                        "{%0,%1,%2,%3}, {%4,%5,%6,%7}, {%8,%9}, {%0,%1,%2,%3};"
                        : "+f"(acc[mi][nj][0]), "+f"(acc[mi][nj][1]),
                          "+f"(acc[mi][nj][2]), "+f"(acc[mi][nj][3])
                        : "r"(a0[mi]), "r"(a1[mi]), "r"(a2[mi]), "r"(a3[mi]),
                          "r"(h0[nj]), "r"(h1[nj]));
                    asm volatile(
                        "mma.sync.aligned.m16n8k16.row.col.f32.bf16.bf16.f32 "
                        "{%0,%1,%2,%3}, {%4,%5,%6,%7}, {%8,%9}, {%0,%1,%2,%3};"
                        : "+f"(acc[mi][nj][0]), "+f"(acc[mi][nj][1]),
                          "+f"(acc[mi][nj][2]), "+f"(acc[mi][nj][3])
                        : "r"(a0[mi]), "r"(a1[mi]), "r"(a2[mi]), "r"(a3[mi]),
                          "r"(l0[nj]), "r"(l1[nj]));
                }
            // Al fragments (reuse a-registers), then Al*Wh
#pragma unroll
            for (int mi = 0; mi < 4; mi++) {
                unsigned addr = buf + AL_OFF +
                    (unsigned)(((wm + mi * 16 + (lane & 15)) * 40 + kk + (lane >> 4) * 8) * 2);
                unsigned r0, r1, r2, r3;
                asm volatile("ldmatrix.sync.aligned.m8n8.x4.shared.b16 {%0,%1,%2,%3}, [%4];"
                             : "=r"(r0), "=r"(r1), "=r"(r2), "=r"(r3) : "r"(addr));
                a0[mi] = r0; a1[mi] = r1; a2[mi] = r2; a3[mi] = r3;
            }
#pragma unroll
            for (int mi = 0; mi < 4; mi++)
#pragma unroll
                for (int nj = 0; nj < 4; nj++) {
                    asm volatile(
                        "mma.sync.aligned.m16n8k16.row.col.f32.bf16.bf16.f32 "
                        "{%0,%1,%2,%3}, {%4,%5,%6,%7}, {%8,%9}, {%0,%1,%2,%3};"
                        : "+f"(acc[mi][nj][0]), "+f"(acc[mi][nj][1]),
                          "+f"(acc[mi][nj][2]), "+f"(acc[mi][nj][3])
                        : "r"(a0[mi]), "r"(a1[mi]), "r"(a2[mi]), "r"(a3[mi]),
                          "r"(h0[nj]), "r"(h1[nj]));
                }
        }
        __syncthreads();
    }

    // ---- epilogue ----
#pragma unroll
    for (int mi = 0; mi < 4; mi++) {
#pragma unroll
        for (int nj = 0; nj < 4; nj++) {
            const int row0 = bm + wm + mi * 16 + (lane >> 2);
            const int col0 = bn + wn + nj * 8 + (lane & 3) * 2;
#pragma unroll
            for (int h = 0; h < 2; h++) {
                const int r = row0 + h * 8;
#pragma unroll
                for (int u = 0; u < 2; u++) {
                    const int c = col0 + u;
                    if (c >= Nout) continue;
                    float v = acc[mi][nj][h * 2 + u] + bias[c];
                    if (mode == 0) {
                        C[(size_t)r * Nout + c] = v;
                    } else {
                        v = gelu_exact(v);
                        __nv_bfloat16 hh = __float2bfloat16(v);
                        Oh[(size_t)r * Nout + c] = hh;
                        Ol[(size_t)r * Nout + c] =
                            __float2bfloat16(v - __bfloat162float(hh));
                    }
                }
            }
        }
    }
}

// ---------------------------------------------------------------------------
// Router final layer: logits[N,5] = (hi+lo)[N,128] @ W[128,5] + b[5]
// ---------------------------------------------------------------------------
__global__ __launch_bounds__(256)
void router_final(const __nv_bfloat16* __restrict__ hh,
                  const __nv_bfloat16* __restrict__ ll,
                  const float* __restrict__ W, const float* __restrict__ b,
                  float* __restrict__ logits) {
    __shared__ float ws[640];
    const int tid = threadIdx.x;
    for (int i = tid; i < 640; i += 256) ws[i] = W[i];
    __syncthreads();
    const int lane = tid & 31;
    const int tok = blockIdx.x * 8 + (tid >> 5);

    const size_t base = (size_t)tok * 128 + lane * 4;
    union { uint2 u; __nv_bfloat16 b[4]; } vh, vl;
    vh.u = *reinterpret_cast<const uint2*>(hh + base);
    vl.u = *reinterpret_cast<const uint2*>(ll + base);

    float p[5] = {0, 0, 0, 0, 0};
#pragma unroll
    for (int k = 0; k < 4; k++) {
        const float x = __bfloat162float(vh.b[k]) + __bfloat162float(vl.b[k]);
        const int kk = lane * 4 + k;
#pragma unroll
        for (int e = 0; e < 5; e++) p[e] = fmaf(x, ws[kk * 5 + e], p[e]);
    }
#pragma unroll
    for (int off = 16; off > 0; off >>= 1)
#pragma unroll
        for (int e = 0; e < 5; e++)
            p[e] += __shfl_down_sync(0xffffffffu, p[e], off);
    if (lane == 0) {
#pragma unroll
        for (int e = 0; e < 5; e++) logits[(size_t)tok * 5 + e] = p[e] + b[e];
    }
}

// ---------------------------------------------------------------------------
// Score final layer: out[N] = (hi+lo)[N,64] @ W[64] + b.
// ---------------------------------------------------------------------------
__global__ __launch_bounds__(256)
void score_final(const __nv_bfloat16* __restrict__ hh,
                 const __nv_bfloat16* __restrict__ ll,
                 const float* __restrict__ W, const float* __restrict__ b,
                 float* __restrict__ out) {
    const int tid = threadIdx.x;
    const int lane = tid & 31;
    const int tok = blockIdx.x * 8 + (tid >> 5);
    const size_t base = (size_t)tok * 64 + lane * 2;
    union { unsigned u; __nv_bfloat16 b[2]; } vh, vl;
    vh.u = *reinterpret_cast<const unsigned*>(hh + base);
    vl.u = *reinterpret_cast<const unsigned*>(ll + base);
    float p = (__bfloat162float(vh.b[0]) + __bfloat162float(vl.b[0])) * W[lane * 2]
            + (__bfloat162float(vh.b[1]) + __bfloat162float(vl.b[1])) * W[lane * 2 + 1];
#pragma unroll
    for (int off = 16; off > 0; off >>= 1)
        p += __shfl_down_sync(0xffffffffu, p, off);
    if (lane == 0) out[tok] = p + b[0];
}

// ---------------------------------------------------------------------------
// Aux-loss
// ---------------------------------------------------------------------------
__global__ void aux_accum(const float* __restrict__ logits, float* __restrict__ part) {
    __shared__ float red[256];
    const int tok = blockIdx.x * 256 + threadIdx.x;
    float l[5];
#pragma unroll
    for (int e = 0; e < 5; e++) l[e] = logits[(size_t)tok * 5 + e];
    float mx = l[0];
#pragma unroll
    for (int e = 1; e < 5; e++) mx = fmaxf(mx, l[e]);
    float p[5], s = 0.0f;
#pragma unroll
    for (int e = 0; e < 5; e++) { p[e] = expf(l[e] - mx); s += p[e]; }
    const float inv = 1.0f / s;
#pragma unroll
    for (int e = 0; e < 5; e++) {
        red[threadIdx.x] = p[e] * inv;
        __syncthreads();
        for (int off = 128; off > 0; off >>= 1) {
            if (threadIdx.x < off) red[threadIdx.x] += red[threadIdx.x + off];
            __syncthreads();
        }
        if (threadIdx.x == 0) part[blockIdx.x * 5 + e] = red[0];
        __syncthreads();
    }
}

__global__ void aux_final(const float* __restrict__ part, float* __restrict__ aux) {
    float s[5] = {0, 0, 0, 0, 0};
    for (int b = 0; b < 192; b++)
#pragma unroll
        for (int e = 0; e < 5; e++) s[e] += part[b * 5 + e];
    float ent = 0.0f, l2 = 0.0f;
#pragma unroll
    for (int e = 0; e < 5; e++) {
        const float a = s[e] / (float)N_TOK;
        ent -= a * logf(a + 1e-8f);
        l2 += (a - 0.2f) * (a - 0.2f);
    }
    l2 *= 0.2f;
    aux[0] = -ent * 0.01f + 0.01f * l2;
}

// ---------------------------------------------------------------------------
// Finalize: top-2 (lowest-index tie-break), softmax-of-2, gather + blend.
// ---------------------------------------------------------------------------
__global__ void finalize_kernel(const float* __restrict__ logits,
                                float* __restrict__ final_traj,
                                float* __restrict__ final_score,
                                float* __restrict__ topk_out,
                                const float* __restrict__ traj_all,
                                const float* __restrict__ score_all) {
    const int tok = blockIdx.x * 4 + (threadIdx.x >> 5);
    const int lane = threadIdx.x & 31;
    if (tok >= N_TOK) return;

    float l[5];
#pragma unroll
    for (int e = 0; e < 5; e++) l[e] = logits[(size_t)tok * 5 + e];

    int i0 = 0; float v0 = l[0];
#pragma unroll
    for (int e = 1; e < 5; e++)
        if (l[e] > v0) { v0 = l[e]; i0 = e; }
    int i1 = -1; float v1 = -3.4e38f;
#pragma unroll
    for (int e = 0; e < 5; e++)
        if (e != i0 && l[e] > v1) { v1 = l[e]; i1 = e; }

    const float e1 = expf(v1 - v0);
    const float inv = 1.0f / (1.0f + e1);
    const float p0 = inv, p1 = e1 * inv;

    if (lane == 0) {
        topk_out[(size_t)tok * 2 + 0] = (float)i0;
        topk_out[(size_t)tok * 2 + 1] = (float)i1;
        const float sh = final_score[tok];
        const float uns = p0 * score_all[(size_t)i0 * N_TOK + tok]
                        + p1 * score_all[(size_t)i1 * N_TOK + tok];
        final_score[tok] = 0.3f * sh + 0.7f * uns;
    }

    const float* t0 = traj_all + (size_t)i0 * N_TOK * 120 + (size_t)tok * 120;
    const float* t1 = traj_all + (size_t)i1 * N_TOK * 120 + (size_t)tok * 120;
    float* ft = final_traj + (size_t)tok * 120;
    for (int t = lane; t < 120; t += 32) {
        const float uns = p0 * t0[t] + p1 * t1[t];
        ft[t] = 0.3f * ft[t] + 0.7f * uns;
    }
}

// ---------------------------------------------------------------------------
// Host launcher (graph-capturable: kernel launches + non-stream APIs only)
// ---------------------------------------------------------------------------
extern "C" void kernel_launch(void* const* d_in, const int* in_sizes, int n_in,
                              void* d_out, int out_size) {
    (void)in_sizes; (void)n_in; (void)out_size;

    cudaFuncSetAttribute(tc_gemm,
                         cudaFuncAttributeMaxDynamicSharedMemorySize, SMEM_TOT);

    __nv_bfloat16 *wh, *wl, *xh, *xl, *ah, *al, *bh, *bl;
    float* part;
    cudaGetSymbolAddress((void**)&wh, g_wh);
    cudaGetSymbolAddress((void**)&wl, g_wl);
    cudaGetSymbolAddress((void**)&xh, g_xh);
    cudaGetSymbolAddress((void**)&xl, g_xl);
    cudaGetSymbolAddress((void**)&ah, g_ah);
    cudaGetSymbolAddress((void**)&al, g_al);
    cudaGetSymbolAddress((void**)&bh, g_bh);
    cudaGetSymbolAddress((void**)&bl, g_bl);
    cudaGetSymbolAddress((void**)&part, g_part);

    const float* in[31];
    for (int i = 0; i < 31; i++) in[i] = (const float*)d_in[i];
    float* out = (float*)d_out;

    float* final_traj  = out + OFF_FINAL_TRAJ;
    float* final_score = out + OFF_FINAL_SCORE;
    float* logits      = out + OFF_LOGITS;
    float* topk        = out + OFF_TOPK;
    float* aux         = out + OFF_AUX;
    float* traj_all    = out + OFF_TRAJ_ALL;
    float* score_all   = out + OFF_SCORE_ALL;

    // ---- split weights + X into hi/lo planes ----
    auto SPLIT = [&](const float* src, int woff, int count) {
        int n4 = count / 4;
        split_kernel<<<(n4 + 255) / 256, 256>>>(src, wh + woff, wl + woff, n4);
    };
    {
        int n4 = (N_TOK * 128) / 4;
        split_kernel<<<(n4 + 255) / 256, 256>>>(in[0], xh, xl, n4);
    }
    SPLIT(in[1],  WOFF_RW1,   32768);
    SPLIT(in[3],  WOFF_RW2,   32768);
    SPLIT(in[7],  WOFF_SHTW1, 32768);
    SPLIT(in[9],  WOFF_SHTW2, 65536);
    SPLIT(in[11], WOFF_SHTW3, 30720);
    SPLIT(in[13], WOFF_SHSW1, 16384);
    SPLIT(in[15], WOFF_SHSW2, 8192);
    SPLIT(in[19], WOFF_EXTW1, 163840);
    SPLIT(in[21], WOFF_EXTW2, 327680);
    SPLIT(in[23], WOFF_EXTW3, 153600);
    SPLIT(in[25], WOFF_EXSW1, 81920);
    SPLIT(in[27], WOFF_EXSW2, 40960);

    // ---- TC GEMM helper ----
    auto G = [&](const __nv_bfloat16* Ah_, const __nv_bfloat16* Al_, int lda,
                 int woff, const float* bias, int Kd, int Nout, int mode,
                 float* C, __nv_bfloat16* Oh_, __nv_bfloat16* Ol_) {
        dim3 grid((Nout + 127) / 128, N_TOK / 128);
        tc_gemm<<<grid, 256, SMEM_TOT>>>(Ah_, Al_, lda, wh + woff, wl + woff,
                                         bias, Kd, Nout, mode, C, Oh_, Ol_);
    };

    // Router: 128 -> 256 -> 128 -> 5
    G(xh, xl, 128, WOFF_RW1, in[2], 128, 256, 1, nullptr, ah, al);
    G(ah, al, 256, WOFF_RW2, in[4], 256, 128, 1, nullptr, bh, bl);
    router_final<<<N_TOK / 8, 256>>>(bh, bl, in[5], in[6], logits);
    aux_accum<<<192, 256>>>(logits, part);
    aux_final<<<1, 1>>>(part, aux);

    // Shared traj: 128 -> 256 -> 256 -> 120
    G(xh, xl, 128, WOFF_SHTW1, in[8],  128, 256, 1, nullptr, ah, al);
    G(ah, al, 256, WOFF_SHTW2, in[10], 256, 256, 1, nullptr, bh, bl);
    G(bh, bl, 256, WOFF_SHTW3, in[12], 256, 120, 0, final_traj, nullptr, nullptr);

    // Shared score: 128 -> 128 -> 64 -> 1
    G(xh, xl, 128, WOFF_SHSW1, in[14], 128, 128, 1, nullptr, ah, al);
    G(ah, al, 128, WOFF_SHSW2, in[16], 128, 64, 1, nullptr, bh, bl);
    score_final<<<N_TOK / 8, 256>>>(bh, bl, in[17], in[18], final_score);

    // Expert traj stacks
    for (int e = 0; e < 5; e++) {
        G(xh, xl, 128, WOFF_EXTW1 + e * 32768, in[20] + (size_t)e * 256,
          128, 256, 1, nullptr, ah, al);
        G(ah, al, 256, WOFF_EXTW2 + e * 65536, in[22] + (size_t)e * 256,
          256, 256, 1, nullptr, bh, bl);
        G(bh, bl, 256, WOFF_EXTW3 + e * 30720, in[24] + (size_t)e * 120,
          256, 120, 0, traj_all + (size_t)e * N_TOK * 120, nullptr, nullptr);
    }

    // Expert score stacks
    for (int e = 0; e < 5; e++) {
        G(xh, xl, 128, WOFF_EXSW1 + e * 16384, in[26] + (size_t)e * 128,
          128, 128, 1, nullptr, ah, al);
        G(ah, al, 128, WOFF_EXSW2 + e * 8192, in[28] + (size_t)e * 64,
          128, 64, 1, nullptr, bh, bl);
        score_final<<<N_TOK / 8, 256>>>(bh, bl, in[29] + (size_t)e * 64,
                                        in[30] + e, score_all + (size_t)e * N_TOK);
    }

    // Top-2 combine + blend
    finalize_kernel<<<N_TOK / 4, 128>>>(logits, final_traj, final_score, topk,
                                        traj_all, score_all);
}

// round 8
// speedup vs baseline: 2.6844x; 1.4616x over previous
#include <cuda_runtime.h>
#include <cuda_bf16.h>
#include <cstdint>
#include <math.h>

// ---------------------------------------------------------------------------
// SupervisedMoEPredictor: B=8192, M=6, D=128, E=5, K=2, T=60. N = 49152.
//
// Output layout (float32):
//   final_traj   [N,120]        @ 0
//   final_score  [N]            @ 5898240
//   router_logits[N,5]          @ 5947392
//   topk_idx     [N,2] (floats) @ 6193152
//   aux_loss     [1]            @ 6291456
//   traj_all     [5,N,120]      @ 6291457
//   score_all    [5,N]          @ 35782657
//
// sm_100 (no 'a' features) -> mma.sync.m16n8k16.bf16, 3-term hi/lo split.
// R7: independent GEMMs batched via blockIdx.z into 6 big launches; RAW-
// separated product passes; cp.async double-buffered staging.
// ---------------------------------------------------------------------------

#define N_TOK 49152

#define OFF_FINAL_TRAJ  0
#define OFF_FINAL_SCORE 5898240
#define OFF_LOGITS      5947392
#define OFF_TOPK        6193152
#define OFF_AUX         6291456
#define OFF_TRAJ_ALL    6291457
#define OFF_SCORE_ALL   35782657

// Weight arena offsets (bf16 elements). Weights [Kd, Nout] row-major,
// grouped contiguously per merged launch.
#define WO_L1W  0        // rw1, sh_tw1, ex_tw1[5]   : 7 x 128x256
#define WO_L1N  229376   // sh_sw1, ex_sw1[5]        : 6 x 128x128
#define WO_L2W  327680   // sh_tw2, ex_tw2[5]        : 6 x 256x256
#define WO_L2R  720896   // rw2                      : 1 x 256x128
#define WO_L2N  753664   // sh_sw2, ex_sw2[5]        : 6 x 128x64
#define WO_L3T  802816   // sh_tw3, ex_tw3[5]        : 6 x 256x120
#define W_ARENA_SZ 987136

// Param arena (fp32): biases + final-score weights
#define BO_L1W  0        // 7 x 256
#define BO_L1N  1792     // 6 x 128
#define BO_L2W  2560     // 6 x 256
#define BO_L2R  4096     // 1 x 128
#define BO_L2N  4224     // 6 x 64
#define BO_L3T  4608     // 6 x 120
#define BO_WSF  5328     // 6 x 64  (score-final weights)
#define BO_BSF  5712     // 6 x 1   (score-final biases)
#define B_ARENA_SZ 5728

__device__ __nv_bfloat16 g_wh[W_ARENA_SZ];
__device__ __nv_bfloat16 g_wl[W_ARENA_SZ];
__device__ float g_barena[B_ARENA_SZ];

__device__ __nv_bfloat16 g_xh[N_TOK * 128];
__device__ __nv_bfloat16 g_xl[N_TOK * 128];
__device__ __nv_bfloat16 g_a1wh[7u * N_TOK * 256];   // L1-wide outs
__device__ __nv_bfloat16 g_a1wl[7u * N_TOK * 256];
__device__ __nv_bfloat16 g_a1nh[6u * N_TOK * 128];   // L1-narrow outs
__device__ __nv_bfloat16 g_a1nl[6u * N_TOK * 128];
__device__ __nv_bfloat16 g_a2wh[6u * N_TOK * 256];   // L2-wide outs
__device__ __nv_bfloat16 g_a2wl[6u * N_TOK * 256];
__device__ __nv_bfloat16 g_a2rh[N_TOK * 128];        // router L2 out
__device__ __nv_bfloat16 g_a2rl[N_TOK * 128];
__device__ __nv_bfloat16 g_a2nh[6u * N_TOK * 64];    // L2-narrow outs
__device__ __nv_bfloat16 g_a2nl[6u * N_TOK * 64];
__device__ float g_part[192 * 5];

// fp32 output offsets for L3-traj units (z=0: final_traj, z>=1: traj_all[e])
__device__ const size_t L3T_OFF[6] =
    {0ull, 6291457ull, 12189697ull, 18087937ull, 23986177ull, 29884417ull};

__device__ __forceinline__ float gelu_exact(float x) {
    return 0.5f * x * (1.0f + erff(x * 0.70710678118654752440f));
}

__device__ __forceinline__ unsigned smem_u32(const void* p) {
    unsigned a;
    asm("{ .reg .u64 t; cvta.to.shared.u64 t, %1; cvt.u32.u64 %0, t; }"
        : "=r"(a) : "l"(p));
    return a;
}

__device__ __forceinline__ void cp16(unsigned dst, const void* src, unsigned sz) {
    asm volatile("cp.async.cg.shared.global [%0], [%1], 16, %2;"
                 :: "r"(dst), "l"(src), "r"(sz));
}
#define CP_COMMIT() asm volatile("cp.async.commit_group;" ::: "memory")
#define CP_WAIT(n)  asm volatile("cp.async.wait_group %0;" :: "n"(n) : "memory")

// SMEM stage layout (bytes): A planes 128x32 (row stride 40 elems),
// W planes 32x128 (row stride 136 elems). Conflict-free for ldmatrix.
#define AH_OFF   0
#define AL_OFF   10240
#define WH_OFF   20480
#define WL_OFF   29184
#define STAGE_B  37888
#define SMEM_TOT (2 * STAGE_B)

// ---------------------------------------------------------------------------
// fp32 -> (hi, lo) bf16 split
// ---------------------------------------------------------------------------
__global__ void split_kernel(const float* __restrict__ src,
                             __nv_bfloat16* __restrict__ hi,
                             __nv_bfloat16* __restrict__ lo, int n4) {
    int i = blockIdx.x * blockDim.x + threadIdx.x;
    if (i >= n4) return;
    float4 v = reinterpret_cast<const float4*>(src)[i];
    union { __nv_bfloat16 b[4]; uint2 u; } H, L;
    float vv[4] = {v.x, v.y, v.z, v.w};
#pragma unroll
    for (int u = 0; u < 4; u++) {
        __nv_bfloat16 h = __float2bfloat16(vv[u]);
        H.b[u] = h;
        L.b[u] = __float2bfloat16(vv[u] - __bfloat162float(h));
    }
    reinterpret_cast<uint2*>(hi)[i] = H.u;
    reinterpret_cast<uint2*>(lo)[i] = L.u;
}

// ---------------------------------------------------------------------------
// Gather biases (+ score-final weights) into the fp32 param arena.
// ---------------------------------------------------------------------------
__global__ void gather_params(float* __restrict__ dst,
    const float* b0, const float* b1, const float* b2, const float* b3,
    const float* b4, const float* b5, const float* b6, const float* b7,
    const float* b8, const float* b9, const float* b10, const float* b11,
    const float* w12, const float* w13, const float* b14, const float* b15) {
    const int t = threadIdx.x;
    auto cp = [&](const float* s, int off, int n) {
        for (int i = t; i < n; i += 256) dst[off + i] = s[i];
    };
    cp(b0, 0, 256);      cp(b1, 256, 256);    cp(b2, 512, 1280);
    cp(b3, 1792, 128);   cp(b4, 1920, 640);
    cp(b5, 2560, 256);   cp(b6, 2816, 1280);
    cp(b7, 4096, 128);
    cp(b8, 4224, 64);    cp(b9, 4288, 320);
    cp(b10, 4608, 120);  cp(b11, 4728, 600);
    cp(w12, 5328, 64);   cp(w13, 5392, 320);
    cp(b14, 5712, 1);    cp(b15, 5713, 5);
}

// ---------------------------------------------------------------------------
// Batched tensor-core GEMM (mma.sync bf16, 3-term hi/lo split):
//   per z: C_z[N_TOK, Nout] = act(A_z @ W_z + bias_z)
// mode 1: gelu -> hi/lo planes. mode 0: fp32 -> Cbase + L3T_OFF[z], no act.
// Tile 128x128x32, 8 warps, warp tile 64x32, cp.async double buffer.
// ---------------------------------------------------------------------------
__global__ __launch_bounds__(256, 2)
void tc_gemm(const __nv_bfloat16* __restrict__ Ah0,
             const __nv_bfloat16* __restrict__ Al0, long long a_zstr, int lda,
             const __nv_bfloat16* __restrict__ Wh0,
             const __nv_bfloat16* __restrict__ Wl0, long long w_zstr,
             int b_off, int b_zstr, int Kd, int Nout, int mode,
             float* __restrict__ Cbase,
             __nv_bfloat16* __restrict__ Oh0,
             __nv_bfloat16* __restrict__ Ol0, long long o_zstr) {
    extern __shared__ char smem[];
    const unsigned sbase = smem_u32(smem);

    const int z = blockIdx.z;
    const __nv_bfloat16* Ah = Ah0 + (size_t)z * a_zstr;
    const __nv_bfloat16* Al = Al0 + (size_t)z * a_zstr;
    const __nv_bfloat16* Wh = Wh0 + (size_t)z * w_zstr;
    const __nv_bfloat16* Wl = Wl0 + (size_t)z * w_zstr;
    const float* bias = g_barena + b_off + z * b_zstr;

    const int tid = threadIdx.x;
    const int lane = tid & 31;
    const int wid = tid >> 5;
    const int bm = blockIdx.y * 128;
    const int bn = blockIdx.x * 128;
    const int wm = (wid >> 2) * 64;
    const int wn = (wid & 3) * 32;

    float acc[4][4][4];
#pragma unroll
    for (int mi = 0; mi < 4; mi++)
#pragma unroll
        for (int nj = 0; nj < 4; nj++)
#pragma unroll
            for (int u = 0; u < 4; u++) acc[mi][nj][u] = 0.0f;

    const int S = Kd >> 5;

    auto load_stage = [&](int s) {
        const unsigned buf = sbase + (unsigned)((s & 1) * STAGE_B);
        const int k0 = s * 32;
#pragma unroll
        for (int t = 0; t < 2; t++) {
            const int chunk = tid + t * 256;
            const int r = chunk >> 2, q = chunk & 3;
            const unsigned doff = (unsigned)((r * 40 + q * 8) * 2);
            const size_t g = (size_t)(bm + r) * lda + k0 + q * 8;
            cp16(buf + AH_OFF + doff, Ah + g, 16u);
            cp16(buf + AL_OFF + doff, Al + g, 16u);
        }
#pragma unroll
        for (int t = 0; t < 2; t++) {
            const int chunk = tid + t * 256;
            const int r = chunk >> 4, q = chunk & 15;
            const int col = bn + q * 8;
            const unsigned ok = (col < Nout) ? 16u : 0u;
            const int csafe = (col < Nout) ? col : 0;
            const unsigned doff = (unsigned)((r * 136 + q * 8) * 2);
            const size_t g = (size_t)(k0 + r) * Nout + csafe;
            cp16(buf + WH_OFF + doff, Wh + g, ok);
            cp16(buf + WL_OFF + doff, Wl + g, ok);
        }
    };

    load_stage(0);
    CP_COMMIT();

    for (int s = 0; s < S; s++) {
        if (s + 1 < S) {
            load_stage(s + 1);
            CP_COMMIT();
            CP_WAIT(1);
        } else {
            CP_WAIT(0);
        }
        __syncthreads();

        const unsigned buf = sbase + (unsigned)((s & 1) * STAGE_B);
#pragma unroll
        for (int kk = 0; kk < 32; kk += 16) {
            unsigned a0[4], a1[4], a2[4], a3[4];
            unsigned h0[4], h1[4], l0[4], l1[4];
#pragma unroll
            for (int mi = 0; mi < 4; mi++) {
                unsigned addr = buf + AH_OFF +
                    (unsigned)(((wm + mi * 16 + (lane & 15)) * 40 + kk + (lane >> 4) * 8) * 2);
                unsigned r0, r1, r2, r3;
                asm volatile("ldmatrix.sync.aligned.m8n8.x4.shared.b16 {%0,%1,%2,%3}, [%4];"
                             : "=r"(r0), "=r"(r1), "=r"(r2), "=r"(r3) : "r"(addr));
                a0[mi] = r0; a1[mi] = r1; a2[mi] = r2; a3[mi] = r3;
            }
            {
                unsigned addr = buf + WH_OFF +
                    (unsigned)(((kk + (lane & 15)) * 136 + wn + (lane >> 4) * 8) * 2);
                unsigned r0, r1, r2, r3;
                asm volatile("ldmatrix.sync.aligned.m8n8.x4.trans.shared.b16 {%0,%1,%2,%3}, [%4];"
                             : "=r"(r0), "=r"(r1), "=r"(r2), "=r"(r3) : "r"(addr));
                h0[0] = r0; h1[0] = r1; h0[1] = r2; h1[1] = r3;
            }
            {
                unsigned addr = buf + WH_OFF +
                    (unsigned)(((kk + (lane & 15)) * 136 + wn + 16 + (lane >> 4) * 8) * 2);
                unsigned r0, r1, r2, r3;
                asm volatile("ldmatrix.sync.aligned.m8n8.x4.trans.shared.b16 {%0,%1,%2,%3}, [%4];"
                             : "=r"(r0), "=r"(r1), "=r"(r2), "=r"(r3) : "r"(addr));
                h0[2] = r0; h1[2] = r1; h0[3] = r2; h1[3] = r3;
            }
            {
                unsigned addr = buf + WL_OFF +
                    (unsigned)(((kk + (lane & 15)) * 136 + wn + (lane >> 4) * 8) * 2);
                unsigned r0, r1, r2, r3;
                asm volatile("ldmatrix.sync.aligned.m8n8.x4.trans.shared.b16 {%0,%1,%2,%3}, [%4];"
                             : "=r"(r0), "=r"(r1), "=r"(r2), "=r"(r3) : "r"(addr));
                l0[0] = r0; l1[0] = r1; l0[1] = r2; l1[1] = r3;
            }
            {
                unsigned addr = buf + WL_OFF +
                    (unsigned)(((kk + (lane & 15)) * 136 + wn + 16 + (lane >> 4) * 8) * 2);
                unsigned r0, r1, r2, r3;
                asm volatile("ldmatrix.sync.aligned.m8n8.x4.trans.shared.b16 {%0,%1,%2,%3}, [%4];"
                             : "=r"(r0), "=r"(r1), "=r"(r2), "=r"(r3) : "r"(addr));
                l0[2] = r0; l1[2] = r1; l0[3] = r2; l1[3] = r3;
            }
            // pass 1: Ah * Wh  (RAW distance 16 on each acc)
#pragma unroll
            for (int mi = 0; mi < 4; mi++)
#pragma unroll
                for (int nj = 0; nj < 4; nj++)
                    asm volatile(
                        "mma.sync.aligned.m16n8k16.row.col.f32.bf16.bf16.f32 "
                        "{%0,%1,%2,%3}, {%4,%5,%6,%7}, {%8,%9}, {%0,%1,%2,%3};"
                        : "+f"(acc[mi][nj][0]), "+f"(acc[mi][nj][1]),
                          "+f"(acc[mi][nj][2]), "+f"(acc[mi][nj][3])
                        : "r"(a0[mi]), "r"(a1[mi]), "r"(a2[mi]), "r"(a3[mi]),
                          "r"(h0[nj]), "r"(h1[nj]));
            // pass 2: Ah * Wl
#pragma unroll
            for (int mi = 0; mi < 4; mi++)
#pragma unroll
                for (int nj = 0; nj < 4; nj++)
                    asm volatile(
                        "mma.sync.aligned.m16n8k16.row.col.f32.bf16.bf16.f32 "
                        "{%0,%1,%2,%3}, {%4,%5,%6,%7}, {%8,%9}, {%0,%1,%2,%3};"
                        : "+f"(acc[mi][nj][0]), "+f"(acc[mi][nj][1]),
                          "+f"(acc[mi][nj][2]), "+f"(acc[mi][nj][3])
                        : "r"(a0[mi]), "r"(a1[mi]), "r"(a2[mi]), "r"(a3[mi]),
                          "r"(l0[nj]), "r"(l1[nj]));
            // pass 3: Al * Wh
#pragma unroll
            for (int mi = 0; mi < 4; mi++) {
                unsigned addr = buf + AL_OFF +
                    (unsigned)(((wm + mi * 16 + (lane & 15)) * 40 + kk + (lane >> 4) * 8) * 2);
                unsigned r0, r1, r2, r3;
                asm volatile("ldmatrix.sync.aligned.m8n8.x4.shared.b16 {%0,%1,%2,%3}, [%4];"
                             : "=r"(r0), "=r"(r1), "=r"(r2), "=r"(r3) : "r"(addr));
                a0[mi] = r0; a1[mi] = r1; a2[mi] = r2; a3[mi] = r3;
            }
#pragma unroll
            for (int mi = 0; mi < 4; mi++)
#pragma unroll
                for (int nj = 0; nj < 4; nj++)
                    asm volatile(
                        "mma.sync.aligned.m16n8k16.row.col.f32.bf16.bf16.f32 "
                        "{%0,%1,%2,%3}, {%4,%5,%6,%7}, {%8,%9}, {%0,%1,%2,%3};"
                        : "+f"(acc[mi][nj][0]), "+f"(acc[mi][nj][1]),
                          "+f"(acc[mi][nj][2]), "+f"(acc[mi][nj][3])
                        : "r"(a0[mi]), "r"(a1[mi]), "r"(a2[mi]), "r"(a3[mi]),
                          "r"(h0[nj]), "r"(h1[nj]));
        }
        __syncthreads();
    }

    // ---- epilogue ----
    float* C = (mode == 0) ? (Cbase + L3T_OFF[z]) : nullptr;
    __nv_bfloat16* Oh = Oh0 + (size_t)z * o_zstr;
    __nv_bfloat16* Ol = Ol0 + (size_t)z * o_zstr;
#pragma unroll
    for (int mi = 0; mi < 4; mi++) {
#pragma unroll
        for (int nj = 0; nj < 4; nj++) {
            const int row0 = bm + wm + mi * 16 + (lane >> 2);
            const int col0 = bn + wn + nj * 8 + (lane & 3) * 2;
#pragma unroll
            for (int h = 0; h < 2; h++) {
                const int r = row0 + h * 8;
#pragma unroll
                for (int u = 0; u < 2; u++) {
                    const int c = col0 + u;
                    if (c >= Nout) continue;
                    float v = acc[mi][nj][h * 2 + u] + bias[c];
                    if (mode == 0) {
                        C[(size_t)r * Nout + c] = v;
                    } else {
                        v = gelu_exact(v);
                        __nv_bfloat16 hh = __float2bfloat16(v);
                        Oh[(size_t)r * Nout + c] = hh;
                        Ol[(size_t)r * Nout + c] =
                            __float2bfloat16(v - __bfloat162float(hh));
                    }
                }
            }
        }
    }
}

// ---------------------------------------------------------------------------
// Router final layer: logits[N,5] = (hi+lo)[N,128] @ W[128,5] + b[5]
// ---------------------------------------------------------------------------
__global__ __launch_bounds__(256)
void router_final(const __nv_bfloat16* __restrict__ hh,
                  const __nv_bfloat16* __restrict__ ll,
                  const float* __restrict__ W, const float* __restrict__ b,
                  float* __restrict__ logits) {
    __shared__ float ws[640];
    const int tid = threadIdx.x;
    for (int i = tid; i < 640; i += 256) ws[i] = W[i];
    __syncthreads();
    const int lane = tid & 31;
    const int tok = blockIdx.x * 8 + (tid >> 5);

    const size_t base = (size_t)tok * 128 + lane * 4;
    union { uint2 u; __nv_bfloat16 b[4]; } vh, vl;
    vh.u = *reinterpret_cast<const uint2*>(hh + base);
    vl.u = *reinterpret_cast<const uint2*>(ll + base);

    float p[5] = {0, 0, 0, 0, 0};
#pragma unroll
    for (int k = 0; k < 4; k++) {
        const float x = __bfloat162float(vh.b[k]) + __bfloat162float(vl.b[k]);
        const int kk = lane * 4 + k;
#pragma unroll
        for (int e = 0; e < 5; e++) p[e] = fmaf(x, ws[kk * 5 + e], p[e]);
    }
#pragma unroll
    for (int off = 16; off > 0; off >>= 1)
#pragma unroll
        for (int e = 0; e < 5; e++)
            p[e] += __shfl_down_sync(0xffffffffu, p[e], off);
    if (lane == 0) {
#pragma unroll
        for (int e = 0; e < 5; e++) logits[(size_t)tok * 5 + e] = p[e] + b[e];
    }
}

// ---------------------------------------------------------------------------
// Merged score-final: z = blockIdx.y. z=0 -> final_score (shared head),
// z>=1 -> score_all[z-1]. A = L2-narrow arena [z][N,64]; W/b from param arena.
// ---------------------------------------------------------------------------
__global__ __launch_bounds__(256)
void score_final_all(const __nv_bfloat16* __restrict__ Ah0,
                     const __nv_bfloat16* __restrict__ Al0,
                     float* __restrict__ out) {
    const int z = blockIdx.y;
    const __nv_bfloat16* hh = Ah0 + (size_t)z * N_TOK * 64;
    const __nv_bfloat16* ll = Al0 + (size_t)z * N_TOK * 64;
    const float* W = g_barena + BO_WSF + z * 64;
    const float bconst = g_barena[BO_BSF + z];
    float* dst = (z == 0) ? (out + OFF_FINAL_SCORE)
                          : (out + OFF_SCORE_ALL + (size_t)(z - 1) * N_TOK);

    const int tid = threadIdx.x;
    const int lane = tid & 31;
    const int tok = blockIdx.x * 8 + (tid >> 5);
    const size_t base = (size_t)tok * 64 + lane * 2;
    union { unsigned u; __nv_bfloat16 b[2]; } vh, vl;
    vh.u = *reinterpret_cast<const unsigned*>(hh + base);
    vl.u = *reinterpret_cast<const unsigned*>(ll + base);
    float p = (__bfloat162float(vh.b[0]) + __bfloat162float(vl.b[0])) * W[lane * 2]
            + (__bfloat162float(vh.b[1]) + __bfloat162float(vl.b[1])) * W[lane * 2 + 1];
#pragma unroll
    for (int off = 16; off > 0; off >>= 1)
        p += __shfl_down_sync(0xffffffffu, p, off);
    if (lane == 0) dst[tok] = p + bconst;
}

// ---------------------------------------------------------------------------
// Aux-loss
// ---------------------------------------------------------------------------
__global__ void aux_accum(const float* __restrict__ logits, float* __restrict__ part) {
    __shared__ float red[256];
    const int tok = blockIdx.x * 256 + threadIdx.x;
    float l[5];
#pragma unroll
    for (int e = 0; e < 5; e++) l[e] = logits[(size_t)tok * 5 + e];
    float mx = l[0];
#pragma unroll
    for (int e = 1; e < 5; e++) mx = fmaxf(mx, l[e]);
    float p[5], s = 0.0f;
#pragma unroll
    for (int e = 0; e < 5; e++) { p[e] = expf(l[e] - mx); s += p[e]; }
    const float inv = 1.0f / s;
#pragma unroll
    for (int e = 0; e < 5; e++) {
        red[threadIdx.x] = p[e] * inv;
        __syncthreads();
        for (int off = 128; off > 0; off >>= 1) {
            if (threadIdx.x < off) red[threadIdx.x] += red[threadIdx.x + off];
            __syncthreads();
        }
        if (threadIdx.x == 0) part[blockIdx.x * 5 + e] = red[0];
        __syncthreads();
    }
}

__global__ void aux_final(const float* __restrict__ part, float* __restrict__ aux) {
    float s[5] = {0, 0, 0, 0, 0};
    for (int b = 0; b < 192; b++)
#pragma unroll
        for (int e = 0; e < 5; e++) s[e] += part[b * 5 + e];
    float ent = 0.0f, l2 = 0.0f;
#pragma unroll
    for (int e = 0; e < 5; e++) {
        const float a = s[e] / (float)N_TOK;
        ent -= a * logf(a + 1e-8f);
        l2 += (a - 0.2f) * (a - 0.2f);
    }
    l2 *= 0.2f;
    aux[0] = -ent * 0.01f + 0.01f * l2;
}

// ---------------------------------------------------------------------------
// Finalize: top-2 (lowest-index tie-break), softmax-of-2, gather + blend.
// ---------------------------------------------------------------------------
__global__ void finalize_kernel(const float* __restrict__ logits,
                                float* __restrict__ final_traj,
                                float* __restrict__ final_score,
                                float* __restrict__ topk_out,
                                const float* __restrict__ traj_all,
                                const float* __restrict__ score_all) {
    const int tok = blockIdx.x * 4 + (threadIdx.x >> 5);
    const int lane = threadIdx.x & 31;
    if (tok >= N_TOK) return;

    float l[5];
#pragma unroll
    for (int e = 0; e < 5; e++) l[e] = logits[(size_t)tok * 5 + e];

    int i0 = 0; float v0 = l[0];
#pragma unroll
    for (int e = 1; e < 5; e++)
        if (l[e] > v0) { v0 = l[e]; i0 = e; }
    int i1 = -1; float v1 = -3.4e38f;
#pragma unroll
    for (int e = 0; e < 5; e++)
        if (e != i0 && l[e] > v1) { v1 = l[e]; i1 = e; }

    const float e1 = expf(v1 - v0);
    const float inv = 1.0f / (1.0f + e1);
    const float p0 = inv, p1 = e1 * inv;

    if (lane == 0) {
        topk_out[(size_t)tok * 2 + 0] = (float)i0;
        topk_out[(size_t)tok * 2 + 1] = (float)i1;
        const float sh = final_score[tok];
        const float uns = p0 * score_all[(size_t)i0 * N_TOK + tok]
                        + p1 * score_all[(size_t)i1 * N_TOK + tok];
        final_score[tok] = 0.3f * sh + 0.7f * uns;
    }

    const float* t0 = traj_all + (size_t)i0 * N_TOK * 120 + (size_t)tok * 120;
    const float* t1 = traj_all + (size_t)i1 * N_TOK * 120 + (size_t)tok * 120;
    float* ft = final_traj + (size_t)tok * 120;
    for (int t = lane; t < 120; t += 32) {
        const float uns = p0 * t0[t] + p1 * t1[t];
        ft[t] = 0.3f * ft[t] + 0.7f * uns;
    }
}

// ---------------------------------------------------------------------------
// Host launcher
// ---------------------------------------------------------------------------
extern "C" void kernel_launch(void* const* d_in, const int* in_sizes, int n_in,
                              void* d_out, int out_size) {
    (void)in_sizes; (void)n_in; (void)out_size;

    cudaFuncSetAttribute(tc_gemm,
                         cudaFuncAttributeMaxDynamicSharedMemorySize, SMEM_TOT);

    __nv_bfloat16 *wh, *wl, *xh, *xl;
    __nv_bfloat16 *a1wh, *a1wl, *a1nh, *a1nl, *a2wh, *a2wl, *a2rh, *a2rl, *a2nh, *a2nl;
    float *barena, *part;
    cudaGetSymbolAddress((void**)&wh, g_wh);
    cudaGetSymbolAddress((void**)&wl, g_wl);
    cudaGetSymbolAddress((void**)&xh, g_xh);
    cudaGetSymbolAddress((void**)&xl, g_xl);
    cudaGetSymbolAddress((void**)&a1wh, g_a1wh);
    cudaGetSymbolAddress((void**)&a1wl, g_a1wl);
    cudaGetSymbolAddress((void**)&a1nh, g_a1nh);
    cudaGetSymbolAddress((void**)&a1nl, g_a1nl);
    cudaGetSymbolAddress((void**)&a2wh, g_a2wh);
    cudaGetSymbolAddress((void**)&a2wl, g_a2wl);
    cudaGetSymbolAddress((void**)&a2rh, g_a2rh);
    cudaGetSymbolAddress((void**)&a2rl, g_a2rl);
    cudaGetSymbolAddress((void**)&a2nh, g_a2nh);
    cudaGetSymbolAddress((void**)&a2nl, g_a2nl);
    cudaGetSymbolAddress((void**)&barena, g_barena);
    cudaGetSymbolAddress((void**)&part, g_part);

    const float* in[31];
    for (int i = 0; i < 31; i++) in[i] = (const float*)d_in[i];
    float* out = (float*)d_out;

    auto SPLIT = [&](const float* src, int woff, int count) {
        int n4 = count / 4;
        split_kernel<<<(n4 + 255) / 256, 256>>>(src, wh + woff, wl + woff, n4);
    };

    // GEMM launcher: z-batched
    auto G = [&](const __nv_bfloat16* Ah_, const __nv_bfloat16* Al_,
                 long long a_zstr, int lda, int woff, long long w_zstr,
                 int b_off, int b_zstr, int Kd, int Nout, int nz, int mode,
                 float* C, __nv_bfloat16* Oh_, __nv_bfloat16* Ol_,
                 long long o_zstr) {
        dim3 grid((Nout + 127) / 128, N_TOK / 128, nz);
        tc_gemm<<<grid, 256, SMEM_TOT>>>(Ah_, Al_, a_zstr, lda,
                                         wh + woff, wl + woff, w_zstr,
                                         b_off, b_zstr, Kd, Nout, mode,
                                         C, Oh_, Ol_, o_zstr);
    };

    const long long ZW = (long long)N_TOK * 256;
    const long long ZN = (long long)N_TOK * 128;
    const long long ZS = (long long)N_TOK * 64;

    // 0-3: X + L1-wide weight splits
    split_kernel<<<(N_TOK * 128 / 4 + 255) / 256, 256>>>(in[0], xh, xl,
                                                         N_TOK * 128 / 4);
    SPLIT(in[1],  WO_L1W,           32768);   // rw1
    SPLIT(in[7],  WO_L1W + 32768,   32768);   // sh_tw1
    SPLIT(in[19], WO_L1W + 65536,  163840);   // ex_tw1[5]
    // 4: param gather
    gather_params<<<1, 256>>>(barena,
        in[2], in[8], in[20], in[14], in[26], in[10], in[22], in[4],
        in[16], in[28], in[12], in[24], in[17], in[29], in[18], in[30]);
    // 5: L1-wide (router, sh traj, 5 expert traj) -- profiled launch
    G(xh, xl, 0, 128, WO_L1W, 32768, BO_L1W, 256, 128, 256, 7, 1,
      nullptr, a1wh, a1wl, ZW);

    // L1-narrow (sh score, 5 expert score)
    SPLIT(in[13], WO_L1N,          16384);    // sh_sw1
    SPLIT(in[25], WO_L1N + 16384,  81920);    // ex_sw1[5]
    G(xh, xl, 0, 128, WO_L1N, 16384, BO_L1N, 128, 128, 128, 6, 1,
      nullptr, a1nh, a1nl, ZN);

    // L2-wide (sh traj L2, 5 expert traj L2): A = a1w units 1..6
    SPLIT(in[9],  WO_L2W,          65536);    // sh_tw2
    SPLIT(in[21], WO_L2W + 65536, 327680);    // ex_tw2[5]
    G(a1wh + ZW, a1wl + ZW, ZW, 256, WO_L2W, 65536, BO_L2W, 256, 256, 256,
      6, 1, nullptr, a2wh, a2wl, ZW);

    // L2-router: A = a1w unit 0
    SPLIT(in[3], WO_L2R, 32768);              // rw2
    G(a1wh, a1wl, 0, 256, WO_L2R, 0, BO_L2R, 0, 256, 128, 1, 1,
      nullptr, a2rh, a2rl, 0);

    // L2-narrow (sh score L2, 5 expert score L2)
    SPLIT(in[15], WO_L2N,          8192);     // sh_sw2
    SPLIT(in[27], WO_L2N + 8192,  40960);     // ex_sw2[5]
    G(a1nh, a1nl, ZN, 128, WO_L2N, 8192, BO_L2N, 64, 128, 64, 6, 1,
      nullptr, a2nh, a2nl, ZS);

    // L3-traj (sh traj L3 -> final_traj, expert traj L3 -> traj_all)
    SPLIT(in[11], WO_L3T,          30720);    // sh_tw3
    SPLIT(in[23], WO_L3T + 30720, 153600);    // ex_tw3[5]
    G(a2wh, a2wl, ZW, 256, WO_L3T, 30720, BO_L3T, 120, 256, 120, 6, 0,
      out, (__nv_bfloat16*)out, (__nv_bfloat16*)out, 0);

    // Router head + aux
    router_final<<<N_TOK / 8, 256>>>(a2rh, a2rl, in[5], in[6],
                                     out + OFF_LOGITS);
    aux_accum<<<192, 256>>>(out + OFF_LOGITS, part);
    aux_final<<<1, 1>>>(part, out + OFF_AUX);

    // Merged score finals
    {
        dim3 grid(N_TOK / 8, 6);
        score_final_all<<<grid, 256>>>(a2nh, a2nl, out);
    }

    // Top-2 combine + blend
    finalize_kernel<<<N_TOK / 4, 128>>>(out + OFF_LOGITS,
                                        out + OFF_FINAL_TRAJ,
                                        out + OFF_FINAL_SCORE,
                                        out + OFF_TOPK,
                                        out + OFF_TRAJ_ALL,
                                        out + OFF_SCORE_ALL);
}

// round 10
// speedup vs baseline: 3.5797x; 1.3335x over previous
#include <cuda_runtime.h>
#include <cuda_bf16.h>
#include <cstdint>
#include <math.h>

// ---------------------------------------------------------------------------
// SupervisedMoEPredictor: B=8192, M=6, D=128, E=5, K=2, T=60. N = 49152.
//
// Output layout (float32):
//   final_traj   [N,120]        @ 0
//   final_score  [N]            @ 5898240
//   router_logits[N,5]          @ 5947392
//   topk_idx     [N,2] (floats) @ 6193152
//   aux_loss     [1]            @ 6291456
//   traj_all     [5,N,120]      @ 6291457   <-- ODD offset: no vector stores!
//   score_all    [5,N]          @ 35782657
//
// sm_100 (no 'a') -> mma.sync.m16n8k16.bf16, 3-term hi/lo split.
// R9: mode-0 epilogue uses scalar stores (traj_all base is odd -> float2
// traps); mode-1 keeps packed bf16x2 stores. Rest identical to R8.
// ---------------------------------------------------------------------------

#define N_TOK 49152

#define OFF_FINAL_TRAJ  0
#define OFF_FINAL_SCORE 5898240
#define OFF_LOGITS      5947392
#define OFF_TOPK        6193152
#define OFF_AUX         6291456
#define OFF_TRAJ_ALL    6291457
#define OFF_SCORE_ALL   35782657

// Weight arena offsets (bf16 elements), [Kd, Nout] row-major, grouped.
#define WO_L1W  0
#define WO_L1N  229376
#define WO_L2W  327680
#define WO_L2R  720896
#define WO_L2N  753664
#define WO_L3T  802816
#define W_ARENA_SZ 987136

// Param arena (fp32)
#define BO_L1W  0
#define BO_L1N  1792
#define BO_L2W  2560
#define BO_L2R  4096
#define BO_L2N  4224
#define BO_L3T  4608
#define BO_WSF  5328
#define BO_BSF  5712
#define B_ARENA_SZ 5728

__device__ __nv_bfloat16 g_wh[W_ARENA_SZ];
__device__ __nv_bfloat16 g_wl[W_ARENA_SZ];
__device__ float g_barena[B_ARENA_SZ];

__device__ __nv_bfloat16 g_xh[N_TOK * 128];
__device__ __nv_bfloat16 g_xl[N_TOK * 128];
__device__ __nv_bfloat16 g_a1wh[7u * N_TOK * 256];
__device__ __nv_bfloat16 g_a1wl[7u * N_TOK * 256];
__device__ __nv_bfloat16 g_a1nh[6u * N_TOK * 128];
__device__ __nv_bfloat16 g_a1nl[6u * N_TOK * 128];
__device__ __nv_bfloat16 g_a2wh[6u * N_TOK * 256];
__device__ __nv_bfloat16 g_a2wl[6u * N_TOK * 256];
__device__ __nv_bfloat16 g_a2rh[N_TOK * 128];
__device__ __nv_bfloat16 g_a2rl[N_TOK * 128];
__device__ __nv_bfloat16 g_a2nh[6u * N_TOK * 64];
__device__ __nv_bfloat16 g_a2nl[6u * N_TOK * 64];
__device__ float g_part[192 * 5];

__device__ const size_t L3T_OFF[6] =
    {0ull, 6291457ull, 12189697ull, 18087937ull, 23986177ull, 29884417ull};

__device__ __forceinline__ float gelu_exact(float x) {
    return 0.5f * x * (1.0f + erff(x * 0.70710678118654752440f));
}

__device__ __forceinline__ unsigned smem_u32(const void* p) {
    unsigned a;
    asm("{ .reg .u64 t; cvta.to.shared.u64 t, %1; cvt.u32.u64 %0, t; }"
        : "=r"(a) : "l"(p));
    return a;
}

__device__ __forceinline__ void cp16(unsigned dst, const void* src, unsigned sz) {
    asm volatile("cp.async.cg.shared.global [%0], [%1], 16, %2;"
                 :: "r"(dst), "l"(src), "r"(sz));
}
#define CP_COMMIT() asm volatile("cp.async.commit_group;" ::: "memory")
#define CP_WAIT(n)  asm volatile("cp.async.wait_group %0;" :: "n"(n) : "memory")

// ---------------------------------------------------------------------------
// fp32 -> (hi, lo) bf16 split
// ---------------------------------------------------------------------------
__global__ void split_kernel(const float* __restrict__ src,
                             __nv_bfloat16* __restrict__ hi,
                             __nv_bfloat16* __restrict__ lo, int n4) {
    int i = blockIdx.x * blockDim.x + threadIdx.x;
    if (i >= n4) return;
    float4 v = reinterpret_cast<const float4*>(src)[i];
    union { __nv_bfloat16 b[4]; uint2 u; } H, L;
    float vv[4] = {v.x, v.y, v.z, v.w};
#pragma unroll
    for (int u = 0; u < 4; u++) {
        __nv_bfloat16 h = __float2bfloat16(vv[u]);
        H.b[u] = h;
        L.b[u] = __float2bfloat16(vv[u] - __bfloat162float(h));
    }
    reinterpret_cast<uint2*>(hi)[i] = H.u;
    reinterpret_cast<uint2*>(lo)[i] = L.u;
}

// 3-range split (rw1 | sh_tw1 | ex_tw1) into a contiguous arena region.
__global__ void split3_kernel(const float* __restrict__ s0,
                              const float* __restrict__ s1,
                              const float* __restrict__ s2,
                              __nv_bfloat16* __restrict__ hi,
                              __nv_bfloat16* __restrict__ lo, int n4) {
    int i = blockIdx.x * blockDim.x + threadIdx.x;
    if (i >= n4) return;
    const float* src;
    int j;
    if (i < 8192)       { src = s0; j = i; }
    else if (i < 16384) { src = s1; j = i - 8192; }
    else                { src = s2; j = i - 16384; }
    float4 v = reinterpret_cast<const float4*>(src)[j];
    union { __nv_bfloat16 b[4]; uint2 u; } H, L;
    float vv[4] = {v.x, v.y, v.z, v.w};
#pragma unroll
    for (int u = 0; u < 4; u++) {
        __nv_bfloat16 h = __float2bfloat16(vv[u]);
        H.b[u] = h;
        L.b[u] = __float2bfloat16(vv[u] - __bfloat162float(h));
    }
    reinterpret_cast<uint2*>(hi)[i] = H.u;
    reinterpret_cast<uint2*>(lo)[i] = L.u;
}

// ---------------------------------------------------------------------------
// Gather biases (+ score-final weights) into fp32 param arena.
// ---------------------------------------------------------------------------
__global__ void gather_params(float* __restrict__ dst,
    const float* b0, const float* b1, const float* b2, const float* b3,
    const float* b4, const float* b5, const float* b6, const float* b7,
    const float* b8, const float* b9, const float* b10, const float* b11,
    const float* w12, const float* w13, const float* b14, const float* b15) {
    const int t = threadIdx.x;
    auto cp = [&](const float* s, int off, int n) {
        for (int i = t; i < n; i += 256) dst[off + i] = s[i];
    };
    cp(b0, 0, 256);      cp(b1, 256, 256);    cp(b2, 512, 1280);
    cp(b3, 1792, 128);   cp(b4, 1920, 640);
    cp(b5, 2560, 256);   cp(b6, 2816, 1280);
    cp(b7, 4096, 128);
    cp(b8, 4224, 64);    cp(b9, 4288, 320);
    cp(b10, 4608, 120);  cp(b11, 4728, 600);
    cp(w12, 5328, 64);   cp(w13, 5392, 320);
    cp(b14, 5712, 1);    cp(b15, 5713, 5);
}

// ---------------------------------------------------------------------------
// Batched tensor-core GEMM (mma.sync bf16, 3-term hi/lo split), templated on
// CTA tile <BM, BN> (8 warps of 64x32) and W smem row stride WSTR.
//   per z: C_z[N_TOK, Nout] = act(A_z @ W_z + bias_z)
// mode 1: gelu -> hi/lo bf16 planes (packed bf16x2 stores).
// mode 0: fp32 -> Cbase + L3T_OFF[z] (SCALAR stores: base may be odd).
// ---------------------------------------------------------------------------
template <int BM, int BN, int WSTR>
__global__ __launch_bounds__(256, 2)
void tc_gemm(const __nv_bfloat16* __restrict__ Ah0,
             const __nv_bfloat16* __restrict__ Al0, long long a_zstr, int lda,
             const __nv_bfloat16* __restrict__ Wh0,
             const __nv_bfloat16* __restrict__ Wl0, long long w_zstr,
             int b_off, int b_zstr, int Kd, int Nout, int mode,
             float* __restrict__ Cbase,
             __nv_bfloat16* __restrict__ Oh0,
             __nv_bfloat16* __restrict__ Ol0, long long o_zstr) {
    constexpr int ASZ = BM * 40 * 2;
    constexpr int WSZ = 32 * WSTR * 2;
    constexpr int AH_OFF = 0;
    constexpr int AL_OFF = ASZ;
    constexpr int WH_OFF = 2 * ASZ;
    constexpr int WL_OFF = 2 * ASZ + WSZ;
    constexpr int STAGE_B = 2 * ASZ + 2 * WSZ;
    constexpr int WNW = BN / 32;

    extern __shared__ char smem[];
    const unsigned sbase = smem_u32(smem);

    const int z = blockIdx.z;
    const __nv_bfloat16* Ah = Ah0 + (size_t)z * a_zstr;
    const __nv_bfloat16* Al = Al0 + (size_t)z * a_zstr;
    const __nv_bfloat16* Wh = Wh0 + (size_t)z * w_zstr;
    const __nv_bfloat16* Wl = Wl0 + (size_t)z * w_zstr;
    const float* bias = g_barena + b_off + z * b_zstr;

    const int tid = threadIdx.x;
    const int lane = tid & 31;
    const int wid = tid >> 5;
    const int bm = blockIdx.y * BM;
    const int bn = blockIdx.x * BN;
    const int wm = (wid / WNW) * 64;
    const int wn = (wid % WNW) * 32;

    float acc[4][4][4];
#pragma unroll
    for (int mi = 0; mi < 4; mi++)
#pragma unroll
        for (int nj = 0; nj < 4; nj++)
#pragma unroll
            for (int u = 0; u < 4; u++) acc[mi][nj][u] = 0.0f;

    const int S = Kd >> 5;

    auto load_stage = [&](int s) {
        const unsigned buf = sbase + (unsigned)((s & 1) * STAGE_B);
        const int k0 = s * 32;
#pragma unroll
        for (int t = 0; t < BM / 64; t++) {
            const int chunk = tid + t * 256;
            const int r = chunk >> 2, q = chunk & 3;
            const unsigned doff = (unsigned)((r * 40 + q * 8) * 2);
            const size_t g = (size_t)(bm + r) * lda + k0 + q * 8;
            cp16(buf + AH_OFF + doff, Ah + g, 16u);
            cp16(buf + AL_OFF + doff, Al + g, 16u);
        }
#pragma unroll
        for (int t = 0; t < BN / 64; t++) {
            const int chunk = tid + t * 256;
            const int r = chunk / (BN / 8), q = chunk % (BN / 8);
            const int col = bn + q * 8;
            const unsigned ok = (col < Nout) ? 16u : 0u;
            const int csafe = (col < Nout) ? col : 0;
            const unsigned doff = (unsigned)((r * WSTR + q * 8) * 2);
            const size_t g = (size_t)(k0 + r) * Nout + csafe;
            cp16(buf + WH_OFF + doff, Wh + g, ok);
            cp16(buf + WL_OFF + doff, Wl + g, ok);
        }
    };

    load_stage(0);
    CP_COMMIT();

    for (int s = 0; s < S; s++) {
        if (s + 1 < S) {
            load_stage(s + 1);
            CP_COMMIT();
            CP_WAIT(1);
        } else {
            CP_WAIT(0);
        }
        __syncthreads();

        const unsigned buf = sbase + (unsigned)((s & 1) * STAGE_B);
#pragma unroll
        for (int kk = 0; kk < 32; kk += 16) {
            unsigned a0[4], a1[4], a2[4], a3[4];
            unsigned h0[4], h1[4], l0[4], l1[4];
#pragma unroll
            for (int mi = 0; mi < 4; mi++) {
                unsigned addr = buf + AH_OFF +
                    (unsigned)(((wm + mi * 16 + (lane & 15)) * 40 + kk + (lane >> 4) * 8) * 2);
                unsigned r0, r1, r2, r3;
                asm volatile("ldmatrix.sync.aligned.m8n8.x4.shared.b16 {%0,%1,%2,%3}, [%4];"
                             : "=r"(r0), "=r"(r1), "=r"(r2), "=r"(r3) : "r"(addr));
                a0[mi] = r0; a1[mi] = r1; a2[mi] = r2; a3[mi] = r3;
            }
            {
                unsigned addr = buf + WH_OFF +
                    (unsigned)(((kk + (lane & 15)) * WSTR + wn + (lane >> 4) * 8) * 2);
                unsigned r0, r1, r2, r3;
                asm volatile("ldmatrix.sync.aligned.m8n8.x4.trans.shared.b16 {%0,%1,%2,%3}, [%4];"
                             : "=r"(r0), "=r"(r1), "=r"(r2), "=r"(r3) : "r"(addr));
                h0[0] = r0; h1[0] = r1; h0[1] = r2; h1[1] = r3;
            }
            {
                unsigned addr = buf + WH_OFF +
                    (unsigned)(((kk + (lane & 15)) * WSTR + wn + 16 + (lane >> 4) * 8) * 2);
                unsigned r0, r1, r2, r3;
                asm volatile("ldmatrix.sync.aligned.m8n8.x4.trans.shared.b16 {%0,%1,%2,%3}, [%4];"
                             : "=r"(r0), "=r"(r1), "=r"(r2), "=r"(r3) : "r"(addr));
                h0[2] = r0; h1[2] = r1; h0[3] = r2; h1[3] = r3;
            }
            {
                unsigned addr = buf + WL_OFF +
                    (unsigned)(((kk + (lane & 15)) * WSTR + wn + (lane >> 4) * 8) * 2);
                unsigned r0, r1, r2, r3;
                asm volatile("ldmatrix.sync.aligned.m8n8.x4.trans.shared.b16 {%0,%1,%2,%3}, [%4];"
                             : "=r"(r0), "=r"(r1), "=r"(r2), "=r"(r3) : "r"(addr));
                l0[0] = r0; l1[0] = r1; l0[1] = r2; l1[1] = r3;
            }
            {
                unsigned addr = buf + WL_OFF +
                    (unsigned)(((kk + (lane & 15)) * WSTR + wn + 16 + (lane >> 4) * 8) * 2);
                unsigned r0, r1, r2, r3;
                asm volatile("ldmatrix.sync.aligned.m8n8.x4.trans.shared.b16 {%0,%1,%2,%3}, [%4];"
                             : "=r"(r0), "=r"(r1), "=r"(r2), "=r"(r3) : "r"(addr));
                l0[2] = r0; l1[2] = r1; l0[3] = r2; l1[3] = r3;
            }
            // pass 1: Ah * Wh
#pragma unroll
            for (int mi = 0; mi < 4; mi++)
#pragma unroll
                for (int nj = 0; nj < 4; nj++)
                    asm volatile(
                        "mma.sync.aligned.m16n8k16.row.col.f32.bf16.bf16.f32 "
                        "{%0,%1,%2,%3}, {%4,%5,%6,%7}, {%8,%9}, {%0,%1,%2,%3};"
                        : "+f"(acc[mi][nj][0]), "+f"(acc[mi][nj][1]),
                          "+f"(acc[mi][nj][2]), "+f"(acc[mi][nj][3])
                        : "r"(a0[mi]), "r"(a1[mi]), "r"(a2[mi]), "r"(a3[mi]),
                          "r"(h0[nj]), "r"(h1[nj]));
            // pass 2: Ah * Wl
#pragma unroll
            for (int mi = 0; mi < 4; mi++)
#pragma unroll
                for (int nj = 0; nj < 4; nj++)
                    asm volatile(
                        "mma.sync.aligned.m16n8k16.row.col.f32.bf16.bf16.f32 "
                        "{%0,%1,%2,%3}, {%4,%5,%6,%7}, {%8,%9}, {%0,%1,%2,%3};"
                        : "+f"(acc[mi][nj][0]), "+f"(acc[mi][nj][1]),
                          "+f"(acc[mi][nj][2]), "+f"(acc[mi][nj][3])
                        : "r"(a0[mi]), "r"(a1[mi]), "r"(a2[mi]), "r"(a3[mi]),
                          "r"(l0[nj]), "r"(l1[nj]));
            // pass 3: Al * Wh
#pragma unroll
            for (int mi = 0; mi < 4; mi++) {
                unsigned addr = buf + AL_OFF +
                    (unsigned)(((wm + mi * 16 + (lane & 15)) * 40 + kk + (lane >> 4) * 8) * 2);
                unsigned r0, r1, r2, r3;
                asm volatile("ldmatrix.sync.aligned.m8n8.x4.shared.b16 {%0,%1,%2,%3}, [%4];"
                             : "=r"(r0), "=r"(r1), "=r"(r2), "=r"(r3) : "r"(addr));
                a0[mi] = r0; a1[mi] = r1; a2[mi] = r2; a3[mi] = r3;
            }
#pragma unroll
            for (int mi = 0; mi < 4; mi++)
#pragma unroll
                for (int nj = 0; nj < 4; nj++)
                    asm volatile(
                        "mma.sync.aligned.m16n8k16.row.col.f32.bf16.bf16.f32 "
                        "{%0,%1,%2,%3}, {%4,%5,%6,%7}, {%8,%9}, {%0,%1,%2,%3};"
                        : "+f"(acc[mi][nj][0]), "+f"(acc[mi][nj][1]),
                          "+f"(acc[mi][nj][2]), "+f"(acc[mi][nj][3])
                        : "r"(a0[mi]), "r"(a1[mi]), "r"(a2[mi]), "r"(a3[mi]),
                          "r"(h0[nj]), "r"(h1[nj]));
        }
        __syncthreads();
    }

    // ---- epilogue ----
    float* C = (mode == 0) ? (Cbase + L3T_OFF[z]) : nullptr;
    __nv_bfloat16* Oh = Oh0 + (size_t)z * o_zstr;
    __nv_bfloat16* Ol = Ol0 + (size_t)z * o_zstr;
#pragma unroll
    for (int mi = 0; mi < 4; mi++) {
#pragma unroll
        for (int nj = 0; nj < 4; nj++) {
            const int row0 = bm + wm + mi * 16 + (lane >> 2);
            const int c0 = bn + wn + nj * 8 + (lane & 3) * 2;
            if (c0 >= Nout) continue;
            const float b0 = bias[c0], b1 = bias[c0 + 1];
#pragma unroll
            for (int h = 0; h < 2; h++) {
                const int r = row0 + h * 8;
                float v0 = acc[mi][nj][h * 2 + 0] + b0;
                float v1 = acc[mi][nj][h * 2 + 1] + b1;
                if (mode == 0) {
                    // SCALAR stores: traj_all base offset is odd (4B-aligned
                    // only) -> float2 would trap.
                    C[(size_t)r * Nout + c0] = v0;
                    C[(size_t)r * Nout + c0 + 1] = v1;
                } else {
                    v0 = gelu_exact(v0);
                    v1 = gelu_exact(v1);
                    __nv_bfloat16 h0b = __float2bfloat16(v0);
                    __nv_bfloat16 h1b = __float2bfloat16(v1);
                    union { __nv_bfloat16 b[2]; unsigned u; } hp, lp;
                    hp.b[0] = h0b; hp.b[1] = h1b;
                    lp.b[0] = __float2bfloat16(v0 - __bfloat162float(h0b));
                    lp.b[1] = __float2bfloat16(v1 - __bfloat162float(h1b));
                    *reinterpret_cast<unsigned*>(Oh + (size_t)r * Nout + c0) = hp.u;
                    *reinterpret_cast<unsigned*>(Ol + (size_t)r * Nout + c0) = lp.u;
                }
            }
        }
    }
}

// ---------------------------------------------------------------------------
// Router final layer: logits[N,5] = (hi+lo)[N,128] @ W[128,5] + b[5]
// ---------------------------------------------------------------------------
__global__ __launch_bounds__(256)
void router_final(const __nv_bfloat16* __restrict__ hh,
                  const __nv_bfloat16* __restrict__ ll,
                  const float* __restrict__ W, const float* __restrict__ b,
                  float* __restrict__ logits) {
    __shared__ float ws[640];
    const int tid = threadIdx.x;
    for (int i = tid; i < 640; i += 256) ws[i] = W[i];
    __syncthreads();
    const int lane = tid & 31;
    const int tok = blockIdx.x * 8 + (tid >> 5);

    const size_t base = (size_t)tok * 128 + lane * 4;
    union { uint2 u; __nv_bfloat16 b[4]; } vh, vl;
    vh.u = *reinterpret_cast<const uint2*>(hh + base);
    vl.u = *reinterpret_cast<const uint2*>(ll + base);

    float p[5] = {0, 0, 0, 0, 0};
#pragma unroll
    for (int k = 0; k < 4; k++) {
        const float x = __bfloat162float(vh.b[k]) + __bfloat162float(vl.b[k]);
        const int kk = lane * 4 + k;
#pragma unroll
        for (int e = 0; e < 5; e++) p[e] = fmaf(x, ws[kk * 5 + e], p[e]);
    }
#pragma unroll
    for (int off = 16; off > 0; off >>= 1)
#pragma unroll
        for (int e = 0; e < 5; e++)
            p[e] += __shfl_down_sync(0xffffffffu, p[e], off);
    if (lane == 0) {
#pragma unroll
        for (int e = 0; e < 5; e++) logits[(size_t)tok * 5 + e] = p[e] + b[e];
    }
}

// ---------------------------------------------------------------------------
// Merged score-final (z=0 -> final_score, z>=1 -> score_all[z-1])
// ---------------------------------------------------------------------------
__global__ __launch_bounds__(256)
void score_final_all(const __nv_bfloat16* __restrict__ Ah0,
                     const __nv_bfloat16* __restrict__ Al0,
                     float* __restrict__ out) {
    const int z = blockIdx.y;
    const __nv_bfloat16* hh = Ah0 + (size_t)z * N_TOK * 64;
    const __nv_bfloat16* ll = Al0 + (size_t)z * N_TOK * 64;
    const float* W = g_barena + BO_WSF + z * 64;
    const float bconst = g_barena[BO_BSF + z];
    float* dst = (z == 0) ? (out + OFF_FINAL_SCORE)
                          : (out + OFF_SCORE_ALL + (size_t)(z - 1) * N_TOK);

    const int tid = threadIdx.x;
    const int lane = tid & 31;
    const int tok = blockIdx.x * 8 + (tid >> 5);
    const size_t base = (size_t)tok * 64 + lane * 2;
    union { unsigned u; __nv_bfloat16 b[2]; } vh, vl;
    vh.u = *reinterpret_cast<const unsigned*>(hh + base);
    vl.u = *reinterpret_cast<const unsigned*>(ll + base);
    float p = (__bfloat162float(vh.b[0]) + __bfloat162float(vl.b[0])) * W[lane * 2]
            + (__bfloat162float(vh.b[1]) + __bfloat162float(vl.b[1])) * W[lane * 2 + 1];
#pragma unroll
    for (int off = 16; off > 0; off >>= 1)
        p += __shfl_down_sync(0xffffffffu, p, off);
    if (lane == 0) dst[tok] = p + bconst;
}

// ---------------------------------------------------------------------------
// Aux-loss
// ---------------------------------------------------------------------------
__global__ void aux_accum(const float* __restrict__ logits, float* __restrict__ part) {
    __shared__ float red[256];
    const int tok = blockIdx.x * 256 + threadIdx.x;
    float l[5];
#pragma unroll
    for (int e = 0; e < 5; e++) l[e] = logits[(size_t)tok * 5 + e];
    float mx = l[0];
#pragma unroll
    for (int e = 1; e < 5; e++) mx = fmaxf(mx, l[e]);
    float p[5], s = 0.0f;
#pragma unroll
    for (int e = 0; e < 5; e++) { p[e] = expf(l[e] - mx); s += p[e]; }
    const float inv = 1.0f / s;
#pragma unroll
    for (int e = 0; e < 5; e++) {
        red[threadIdx.x] = p[e] * inv;
        __syncthreads();
        for (int off = 128; off > 0; off >>= 1) {
            if (threadIdx.x < off) red[threadIdx.x] += red[threadIdx.x + off];
            __syncthreads();
        }
        if (threadIdx.x == 0) part[blockIdx.x * 5 + e] = red[0];
        __syncthreads();
    }
}

__global__ void aux_final(const float* __restrict__ part, float* __restrict__ aux) {
    float s[5] = {0, 0, 0, 0, 0};
    for (int b = 0; b < 192; b++)
#pragma unroll
        for (int e = 0; e < 5; e++) s[e] += part[b * 5 + e];
    float ent = 0.0f, l2 = 0.0f;
#pragma unroll
    for (int e = 0; e < 5; e++) {
        const float a = s[e] / (float)N_TOK;
        ent -= a * logf(a + 1e-8f);
        l2 += (a - 0.2f) * (a - 0.2f);
    }
    l2 *= 0.2f;
    aux[0] = -ent * 0.01f + 0.01f * l2;
}

// ---------------------------------------------------------------------------
// Finalize: top-2 (lowest-index tie-break), softmax-of-2, gather + blend.
// ---------------------------------------------------------------------------
__global__ void finalize_kernel(const float* __restrict__ logits,
                                float* __restrict__ final_traj,
                                float* __restrict__ final_score,
                                float* __restrict__ topk_out,
                                const float* __restrict__ traj_all,
                                const float* __restrict__ score_all) {
    const int tok = blockIdx.x * 4 + (threadIdx.x >> 5);
    const int lane = threadIdx.x & 31;
    if (tok >= N_TOK) return;

    float l[5];
#pragma unroll
    for (int e = 0; e < 5; e++) l[e] = logits[(size_t)tok * 5 + e];

    int i0 = 0; float v0 = l[0];
#pragma unroll
    for (int e = 1; e < 5; e++)
        if (l[e] > v0) { v0 = l[e]; i0 = e; }
    int i1 = -1; float v1 = -3.4e38f;
#pragma unroll
    for (int e = 0; e < 5; e++)
        if (e != i0 && l[e] > v1) { v1 = l[e]; i1 = e; }

    const float e1 = expf(v1 - v0);
    const float inv = 1.0f / (1.0f + e1);
    const float p0 = inv, p1 = e1 * inv;

    if (lane == 0) {
        topk_out[(size_t)tok * 2 + 0] = (float)i0;
        topk_out[(size_t)tok * 2 + 1] = (float)i1;
        const float sh = final_score[tok];
        const float uns = p0 * score_all[(size_t)i0 * N_TOK + tok]
                        + p1 * score_all[(size_t)i1 * N_TOK + tok];
        final_score[tok] = 0.3f * sh + 0.7f * uns;
    }

    const float* t0 = traj_all + (size_t)i0 * N_TOK * 120 + (size_t)tok * 120;
    const float* t1 = traj_all + (size_t)i1 * N_TOK * 120 + (size_t)tok * 120;
    float* ft = final_traj + (size_t)tok * 120;
    for (int t = lane; t < 120; t += 32) {
        const float uns = p0 * t0[t] + p1 * t1[t];
        ft[t] = 0.3f * ft[t] + 0.7f * uns;
    }
}

// ---------------------------------------------------------------------------
// Host launcher
// ---------------------------------------------------------------------------
extern "C" void kernel_launch(void* const* d_in, const int* in_sizes, int n_in,
                              void* d_out, int out_size) {
    (void)in_sizes; (void)n_in; (void)out_size;

    cudaFuncSetAttribute(tc_gemm<128, 128, 136>,
                         cudaFuncAttributeMaxDynamicSharedMemorySize, 75776);
    cudaFuncSetAttribute(tc_gemm<256, 64, 72>,
                         cudaFuncAttributeMaxDynamicSharedMemorySize, 100352);

    __nv_bfloat16 *wh, *wl, *xh, *xl;
    __nv_bfloat16 *a1wh, *a1wl, *a1nh, *a1nl, *a2wh, *a2wl, *a2rh, *a2rl, *a2nh, *a2nl;
    float *barena, *part;
    cudaGetSymbolAddress((void**)&wh, g_wh);
    cudaGetSymbolAddress((void**)&wl, g_wl);
    cudaGetSymbolAddress((void**)&xh, g_xh);
    cudaGetSymbolAddress((void**)&xl, g_xl);
    cudaGetSymbolAddress((void**)&a1wh, g_a1wh);
    cudaGetSymbolAddress((void**)&a1wl, g_a1wl);
    cudaGetSymbolAddress((void**)&a1nh, g_a1nh);
    cudaGetSymbolAddress((void**)&a1nl, g_a1nl);
    cudaGetSymbolAddress((void**)&a2wh, g_a2wh);
    cudaGetSymbolAddress((void**)&a2wl, g_a2wl);
    cudaGetSymbolAddress((void**)&a2rh, g_a2rh);
    cudaGetSymbolAddress((void**)&a2rl, g_a2rl);
    cudaGetSymbolAddress((void**)&a2nh, g_a2nh);
    cudaGetSymbolAddress((void**)&a2nl, g_a2nl);
    cudaGetSymbolAddress((void**)&barena, g_barena);
    cudaGetSymbolAddress((void**)&part, g_part);

    const float* in[31];
    for (int i = 0; i < 31; i++) in[i] = (const float*)d_in[i];
    float* out = (float*)d_out;

    auto SPLIT = [&](const float* src, int woff, int count) {
        int n4 = count / 4;
        split_kernel<<<(n4 + 255) / 256, 256>>>(src, wh + woff, wl + woff, n4);
    };

    auto G128 = [&](const __nv_bfloat16* Ah_, const __nv_bfloat16* Al_,
                    long long a_zstr, int lda, int woff, long long w_zstr,
                    int b_off, int b_zstr, int Kd, int Nout, int nz, int mode,
                    float* C, __nv_bfloat16* Oh_, __nv_bfloat16* Ol_,
                    long long o_zstr) {
        dim3 grid((Nout + 127) / 128, N_TOK / 128, nz);
        tc_gemm<128, 128, 136><<<grid, 256, 75776>>>(
            Ah_, Al_, a_zstr, lda, wh + woff, wl + woff, w_zstr,
            b_off, b_zstr, Kd, Nout, mode, C, Oh_, Ol_, o_zstr);
    };

    const long long ZW = (long long)N_TOK * 256;
    const long long ZN = (long long)N_TOK * 128;
    const long long ZS = (long long)N_TOK * 64;

    // Launch order: 0=splitX, 1=split3(L1W), 2=gather, 3=L1-wide GEMM
    split_kernel<<<(N_TOK * 128 / 4 + 255) / 256, 256>>>(in[0], xh, xl,
                                                         N_TOK * 128 / 4);
    split3_kernel<<<(57344 + 255) / 256, 256>>>(in[1], in[7], in[19],
                                                wh + WO_L1W, wl + WO_L1W, 57344);
    gather_params<<<1, 256>>>(barena,
        in[2], in[8], in[20], in[14], in[26], in[10], in[22], in[4],
        in[16], in[28], in[12], in[24], in[17], in[29], in[18], in[30]);
    // L1-wide (router, sh traj, 5 expert traj) — profiled slot
    G128(xh, xl, 0, 128, WO_L1W, 32768, BO_L1W, 256, 128, 256, 7, 1,
         nullptr, a1wh, a1wl, ZW);

    // L1-narrow (sh score, 5 expert score)
    SPLIT(in[13], WO_L1N,          16384);
    SPLIT(in[25], WO_L1N + 16384,  81920);
    G128(xh, xl, 0, 128, WO_L1N, 16384, BO_L1N, 128, 128, 128, 6, 1,
         nullptr, a1nh, a1nl, ZN);

    // L2-wide (sh traj L2, 5 expert traj L2)
    SPLIT(in[9],  WO_L2W,          65536);
    SPLIT(in[21], WO_L2W + 65536, 327680);
    G128(a1wh + ZW, a1wl + ZW, ZW, 256, WO_L2W, 65536, BO_L2W, 256, 256, 256,
         6, 1, nullptr, a2wh, a2wl, ZW);

    // L2-router
    SPLIT(in[3], WO_L2R, 32768);
    G128(a1wh, a1wl, 0, 256, WO_L2R, 0, BO_L2R, 0, 256, 128, 1, 1,
         nullptr, a2rh, a2rl, 0);

    // L2-narrow (Nout=64): 256x64 tile variant
    SPLIT(in[15], WO_L2N,          8192);
    SPLIT(in[27], WO_L2N + 8192,  40960);
    {
        dim3 grid(1, N_TOK / 256, 6);
        tc_gemm<256, 64, 72><<<grid, 256, 100352>>>(
            a1nh, a1nl, ZN, 128, wh + WO_L2N, wl + WO_L2N, 8192,
            BO_L2N, 64, 128, 64, 1, nullptr, a2nh, a2nl, ZS);
    }

    // L3-traj (sh -> final_traj, experts -> traj_all)
    SPLIT(in[11], WO_L3T,          30720);
    SPLIT(in[23], WO_L3T + 30720, 153600);
    G128(a2wh, a2wl, ZW, 256, WO_L3T, 30720, BO_L3T, 120, 256, 120, 6, 0,
         out, (__nv_bfloat16*)out, (__nv_bfloat16*)out, 0);

    // Router head + aux
    router_final<<<N_TOK / 8, 256>>>(a2rh, a2rl, in[5], in[6],
                                     out + OFF_LOGITS);
    aux_accum<<<192, 256>>>(out + OFF_LOGITS, part);
    aux_final<<<1, 1>>>(part, out + OFF_AUX);

    // Merged score finals
    {
        dim3 grid(N_TOK / 8, 6);
        score_final_all<<<grid, 256>>>(a2nh, a2nl, out);
    }

    // Top-2 combine + blend
    finalize_kernel<<<N_TOK / 4, 128>>>(out + OFF_LOGITS,
                                        out + OFF_FINAL_TRAJ,
                                        out + OFF_FINAL_SCORE,
                                        out + OFF_TOPK,
                                        out + OFF_TRAJ_ALL,
                                        out + OFF_SCORE_ALL);
}

// round 12
// speedup vs baseline: 3.6838x; 1.0291x over previous
#include <cuda_runtime.h>
#include <cuda_bf16.h>
#include <cstdint>
#include <math.h>

// ---------------------------------------------------------------------------
// SupervisedMoEPredictor: B=8192, M=6, D=128, E=5, K=2, T=60. N = 49152.
//
// Output layout (float32):
//   final_traj   [N,120]        @ 0
//   final_score  [N]            @ 5898240
//   router_logits[N,5]          @ 5947392
//   topk_idx     [N,2] (floats) @ 6193152
//   aux_loss     [1]            @ 6291456
//   traj_all     [5,N,120]      @ 6291457   <-- ODD offset: scalar stores only
//   score_all    [5,N]          @ 35782657
//
// sm_100 (no 'a') -> mma.sync.m16n8k16.bf16, 3-term hi/lo split.
// R11: identical resubmit of R10 (container-level failure, no kernel signal):
// hoisted ldmatrix addressing, packed bf16x2 epilogue conversions, merged
// weight-split kernel.
// ---------------------------------------------------------------------------

#define N_TOK 49152

#define OFF_FINAL_TRAJ  0
#define OFF_FINAL_SCORE 5898240
#define OFF_LOGITS      5947392
#define OFF_TOPK        6193152
#define OFF_AUX         6291456
#define OFF_TRAJ_ALL   6291457
#define OFF_SCORE_ALL   35782657

// Weight arena offsets (bf16 elements), [Kd, Nout] row-major, contiguous.
#define WO_L1W  0
#define WO_L1N  229376
#define WO_L2W  327680
#define WO_L2R  720896
#define WO_L2N  753664
#define WO_L3T  802816
#define W_ARENA_SZ 987136

// Param arena (fp32)
#define BO_L1W  0
#define BO_L1N  1792
#define BO_L2W  2560
#define BO_L2R  4096
#define BO_L2N  4224
#define BO_L3T  4608
#define BO_WSF  5328
#define BO_BSF  5712
#define B_ARENA_SZ 5728

__device__ __nv_bfloat16 g_wh[W_ARENA_SZ];
__device__ __nv_bfloat16 g_wl[W_ARENA_SZ];
__device__ float g_barena[B_ARENA_SZ];

__device__ __nv_bfloat16 g_xh[N_TOK * 128];
__device__ __nv_bfloat16 g_xl[N_TOK * 128];
__device__ __nv_bfloat16 g_a1wh[7u * N_TOK * 256];
__device__ __nv_bfloat16 g_a1wl[7u * N_TOK * 256];
__device__ __nv_bfloat16 g_a1nh[6u * N_TOK * 128];
__device__ __nv_bfloat16 g_a1nl[6u * N_TOK * 128];
__device__ __nv_bfloat16 g_a2wh[6u * N_TOK * 256];
__device__ __nv_bfloat16 g_a2wl[6u * N_TOK * 256];
__device__ __nv_bfloat16 g_a2rh[N_TOK * 128];
__device__ __nv_bfloat16 g_a2rl[N_TOK * 128];
__device__ __nv_bfloat16 g_a2nh[6u * N_TOK * 64];
__device__ __nv_bfloat16 g_a2nl[6u * N_TOK * 64];
__device__ float g_part[192 * 5];

__device__ const size_t L3T_OFF[6] =
    {0ull, 6291457ull, 12189697ull, 18087937ull, 23986177ull, 29884417ull};

__device__ __forceinline__ float gelu_exact(float x) {
    return 0.5f * x * (1.0f + erff(x * 0.70710678118654752440f));
}

__device__ __forceinline__ unsigned smem_u32(const void* p) {
    unsigned a;
    asm("{ .reg .u64 t; cvta.to.shared.u64 t, %1; cvt.u32.u64 %0, t; }"
        : "=r"(a) : "l"(p));
    return a;
}

__device__ __forceinline__ void cp16(unsigned dst, const void* src, unsigned sz) {
    asm volatile("cp.async.cg.shared.global [%0], [%1], 16, %2;"
                 :: "r"(dst), "l"(src), "r"(sz));
}
#define CP_COMMIT() asm volatile("cp.async.commit_group;" ::: "memory")
#define CP_WAIT(n)  asm volatile("cp.async.wait_group %0;" :: "n"(n) : "memory")

#define LDMX4(r0, r1, r2, r3, addr) \
    asm volatile("ldmatrix.sync.aligned.m8n8.x4.shared.b16 {%0,%1,%2,%3}, [%4];" \
                 : "=r"(r0), "=r"(r1), "=r"(r2), "=r"(r3) : "r"(addr))
#define LDMX4T(r0, r1, r2, r3, addr) \
    asm volatile("ldmatrix.sync.aligned.m8n8.x4.trans.shared.b16 {%0,%1,%2,%3}, [%4];" \
                 : "=r"(r0), "=r"(r1), "=r"(r2), "=r"(r3) : "r"(addr))
#define MMA16816(acc, a0, a1, a2, a3, b0, b1) \
    asm volatile("mma.sync.aligned.m16n8k16.row.col.f32.bf16.bf16.f32 " \
                 "{%0,%1,%2,%3}, {%4,%5,%6,%7}, {%8,%9}, {%0,%1,%2,%3};" \
                 : "+f"((acc)[0]), "+f"((acc)[1]), "+f"((acc)[2]), "+f"((acc)[3]) \
                 : "r"(a0), "r"(a1), "r"(a2), "r"(a3), "r"(b0), "r"(b1))

// ---------------------------------------------------------------------------
// fp32 -> (hi, lo) bf16 split (X only)
// ---------------------------------------------------------------------------
__global__ void split_kernel(const float* __restrict__ src,
                             __nv_bfloat16* __restrict__ hi,
                             __nv_bfloat16* __restrict__ lo, int n4) {
    int i = blockIdx.x * blockDim.x + threadIdx.x;
    if (i >= n4) return;
    float4 v = reinterpret_cast<const float4*>(src)[i];
    union { __nv_bfloat16 b[4]; uint2 u; } H, L;
    float vv[4] = {v.x, v.y, v.z, v.w};
#pragma unroll
    for (int u = 0; u < 4; u++) {
        __nv_bfloat16 h = __float2bfloat16(vv[u]);
        H.b[u] = h;
        L.b[u] = __float2bfloat16(vv[u] - __bfloat162float(h));
    }
    reinterpret_cast<uint2*>(hi)[i] = H.u;
    reinterpret_cast<uint2*>(lo)[i] = L.u;
}

// ---------------------------------------------------------------------------
// ALL 12 weight splits in one kernel. Dst arena is contiguous [0, 987136).
// Segment boundaries in float4 units.
// ---------------------------------------------------------------------------
__global__ void splitw_all(
    const float* __restrict__ s0,  const float* __restrict__ s1,
    const float* __restrict__ s2,  const float* __restrict__ s3,
    const float* __restrict__ s4,  const float* __restrict__ s5,
    const float* __restrict__ s6,  const float* __restrict__ s7,
    const float* __restrict__ s8,  const float* __restrict__ s9,
    const float* __restrict__ s10, const float* __restrict__ s11,
    __nv_bfloat16* __restrict__ hi, __nv_bfloat16* __restrict__ lo) {
    int i = blockIdx.x * blockDim.x + threadIdx.x;
    if (i >= 246784) return;
    const float* src; int j;
    if (i < 57344) {
        if (i < 8192)       { src = s0; j = i; }
        else if (i < 16384) { src = s1; j = i - 8192; }
        else                { src = s2; j = i - 16384; }
    } else if (i < 98304) {
        if (i < 61440)      { src = s3; j = i - 57344; }
        else if (i < 81920) { src = s4; j = i - 61440; }
        else                { src = s5; j = i - 81920; }
    } else if (i < 190464) {
        if (i < 180224)      { src = s6; j = i - 98304; }
        else if (i < 188416) { src = s7; j = i - 180224; }
        else                 { src = s8; j = i - 188416; }
    } else {
        if (i < 200704)      { src = s9; j = i - 190464; }
        else if (i < 208384) { src = s10; j = i - 200704; }
        else                 { src = s11; j = i - 208384; }
    }
    float4 v = reinterpret_cast<const float4*>(src)[j];
    union { __nv_bfloat16 b[4]; uint2 u; } H, L;
    float vv[4] = {v.x, v.y, v.z, v.w};
#pragma unroll
    for (int u = 0; u < 4; u++) {
        __nv_bfloat16 h = __float2bfloat16(vv[u]);
        H.b[u] = h;
        L.b[u] = __float2bfloat16(vv[u] - __bfloat162float(h));
    }
    reinterpret_cast<uint2*>(hi)[i] = H.u;
    reinterpret_cast<uint2*>(lo)[i] = L.u;
}

// ---------------------------------------------------------------------------
// Gather biases (+ score-final weights) into fp32 param arena.
// ---------------------------------------------------------------------------
__global__ void gather_params(float* __restrict__ dst,
    const float* b0, const float* b1, const float* b2, const float* b3,
    const float* b4, const float* b5, const float* b6, const float* b7,
    const float* b8, const float* b9, const float* b10, const float* b11,
    const float* w12, const float* w13, const float* b14, const float* b15) {
    const int t = threadIdx.x;
    auto cp = [&](const float* s, int off, int n) {
        for (int i = t; i < n; i += 256) dst[off + i] = s[i];
    };
    cp(b0, 0, 256);      cp(b1, 256, 256);    cp(b2, 512, 1280);
    cp(b3, 1792, 128);   cp(b4, 1920, 640);
    cp(b5, 2560, 256);   cp(b6, 2816, 1280);
    cp(b7, 4096, 128);
    cp(b8, 4224, 64);    cp(b9, 4288, 320);
    cp(b10, 4608, 120);  cp(b11, 4728, 600);
    cp(w12, 5328, 64);   cp(w13, 5392, 320);
    cp(b14, 5712, 1);    cp(b15, 5713, 5);
}

// ---------------------------------------------------------------------------
// Batched tensor-core GEMM (mma.sync bf16, 3-term hi/lo split), templated on
// CTA tile <BM, BN> (8 warps of 64x32) and W smem row stride WSTR.
//   per z: C_z[N_TOK, Nout] = act(A_z @ W_z + bias_z)
// mode 1: gelu -> hi/lo bf16 planes (packed bf16x2 conversions + stores).
// mode 0: fp32 -> Cbase + L3T_OFF[z] (SCALAR stores: base may be odd).
// ---------------------------------------------------------------------------
template <int BM, int BN, int WSTR>
__global__ __launch_bounds__(256, 2)
void tc_gemm(const __nv_bfloat16* __restrict__ Ah0,
             const __nv_bfloat16* __restrict__ Al0, long long a_zstr, int lda,
             const __nv_bfloat16* __restrict__ Wh0,
             const __nv_bfloat16* __restrict__ Wl0, long long w_zstr,
             int b_off, int b_zstr, int Kd, int Nout, int mode,
             float* __restrict__ Cbase,
             __nv_bfloat16* __restrict__ Oh0,
             __nv_bfloat16* __restrict__ Ol0, long long o_zstr) {
    constexpr int ASZ = BM * 40 * 2;
    constexpr int WSZ = 32 * WSTR * 2;
    constexpr int AH_OFF = 0;
    constexpr int AL_OFF = ASZ;
    constexpr int WH_OFF = 2 * ASZ;
    constexpr int WL_OFF = 2 * ASZ + WSZ;
    constexpr int STAGE_B = 2 * ASZ + 2 * WSZ;
    constexpr int WNW = BN / 32;

    extern __shared__ char smem[];
    const unsigned sbase = smem_u32(smem);

    const int z = blockIdx.z;
    const __nv_bfloat16* Ah = Ah0 + (size_t)z * a_zstr;
    const __nv_bfloat16* Al = Al0 + (size_t)z * a_zstr;
    const __nv_bfloat16* Wh = Wh0 + (size_t)z * w_zstr;
    const __nv_bfloat16* Wl = Wl0 + (size_t)z * w_zstr;
    const float* bias = g_barena + b_off + z * b_zstr;

    const int tid = threadIdx.x;
    const int lane = tid & 31;
    const int wid = tid >> 5;
    const int bm = blockIdx.y * BM;
    const int bn = blockIdx.x * BN;
    const int wm = (wid / WNW) * 64;
    const int wn = (wid % WNW) * 32;

    // Per-warp invariant ldmatrix lane offsets (bytes)
    const unsigned aoff = (unsigned)(((wm + (lane & 15)) * 40 + (lane >> 4) * 8) * 2);
    const unsigned woff = (unsigned)(((lane & 15) * WSTR + wn + (lane >> 4) * 8) * 2);

    float acc[4][4][4];
#pragma unroll
    for (int mi = 0; mi < 4; mi++)
#pragma unroll
        for (int nj = 0; nj < 4; nj++)
#pragma unroll
            for (int u = 0; u < 4; u++) acc[mi][nj][u] = 0.0f;

    const int S = Kd >> 5;

    auto load_stage = [&](int s) {
        const unsigned buf = sbase + (unsigned)((s & 1) * STAGE_B);
        const int k0 = s * 32;
#pragma unroll
        for (int t = 0; t < BM / 64; t++) {
            const int chunk = tid + t * 256;
            const int r = chunk >> 2, q = chunk & 3;
            const unsigned doff = (unsigned)((r * 40 + q * 8) * 2);
            const size_t g = (size_t)(bm + r) * lda + k0 + q * 8;
            cp16(buf + AH_OFF + doff, Ah + g, 16u);
            cp16(buf + AL_OFF + doff, Al + g, 16u);
        }
#pragma unroll
        for (int t = 0; t < BN / 64; t++) {
            const int chunk = tid + t * 256;
            const int r = chunk / (BN / 8), q = chunk % (BN / 8);
            const int col = bn + q * 8;
            const unsigned ok = (col < Nout) ? 16u : 0u;
            const int csafe = (col < Nout) ? col : 0;
            const unsigned doff = (unsigned)((r * WSTR + q * 8) * 2);
            const size_t g = (size_t)(k0 + r) * Nout + csafe;
            cp16(buf + WH_OFF + doff, Wh + g, ok);
            cp16(buf + WL_OFF + doff, Wl + g, ok);
        }
    };

    load_stage(0);
    CP_COMMIT();

    for (int s = 0; s < S; s++) {
        if (s + 1 < S) {
            load_stage(s + 1);
            CP_COMMIT();
            CP_WAIT(1);
        } else {
            CP_WAIT(0);
        }
        __syncthreads();

        // Stage-invariant base addresses (1 add per ldmatrix below)
        const unsigned bufb = sbase + (unsigned)((s & 1) * STAGE_B);
        const unsigned ah_b = bufb + AH_OFF + aoff;
        const unsigned al_b = bufb + AL_OFF + aoff;
        const unsigned wh_b = bufb + WH_OFF + woff;
        const unsigned wl_b = bufb + WL_OFF + woff;

#pragma unroll
        for (int kk = 0; kk < 32; kk += 16) {
            unsigned a0[4], a1[4], a2[4], a3[4];
            unsigned h0[4], h1[4], l0[4], l1[4];
#pragma unroll
            for (int mi = 0; mi < 4; mi++)
                LDMX4(a0[mi], a1[mi], a2[mi], a3[mi],
                      ah_b + (unsigned)((mi * 640 + kk) * 2));
            LDMX4T(h0[0], h1[0], h0[1], h1[1],
                   wh_b + (unsigned)((kk * WSTR) * 2));
            LDMX4T(h0[2], h1[2], h0[3], h1[3],
                   wh_b + (unsigned)((kk * WSTR + 16) * 2));
            LDMX4T(l0[0], l1[0], l0[1], l1[1],
                   wl_b + (unsigned)((kk * WSTR) * 2));
            LDMX4T(l0[2], l1[2], l0[3], l1[3],
                   wl_b + (unsigned)((kk * WSTR + 16) * 2));
            // pass 1: Ah * Wh
#pragma unroll
            for (int mi = 0; mi < 4; mi++)
#pragma unroll
                for (int nj = 0; nj < 4; nj++)
                    MMA16816(acc[mi][nj], a0[mi], a1[mi], a2[mi], a3[mi],
                             h0[nj], h1[nj]);
            // pass 2: Ah * Wl
#pragma unroll
            for (int mi = 0; mi < 4; mi++)
#pragma unroll
                for (int nj = 0; nj < 4; nj++)
                    MMA16816(acc[mi][nj], a0[mi], a1[mi], a2[mi], a3[mi],
                             l0[nj], l1[nj]);
            // pass 3: Al * Wh (reload A from lo plane)
#pragma unroll
            for (int mi = 0; mi < 4; mi++)
                LDMX4(a0[mi], a1[mi], a2[mi], a3[mi],
                      al_b + (unsigned)((mi * 640 + kk) * 2));
#pragma unroll
            for (int mi = 0; mi < 4; mi++)
#pragma unroll
                for (int nj = 0; nj < 4; nj++)
                    MMA16816(acc[mi][nj], a0[mi], a1[mi], a2[mi], a3[mi],
                             h0[nj], h1[nj]);
        }
        __syncthreads();
    }

    // ---- epilogue ----
    float* C = (mode == 0) ? (Cbase + L3T_OFF[z]) : nullptr;
    __nv_bfloat16* Oh = Oh0 + (size_t)z * o_zstr;
    __nv_bfloat16* Ol = Ol0 + (size_t)z * o_zstr;
#pragma unroll
    for (int mi = 0; mi < 4; mi++) {
#pragma unroll
        for (int nj = 0; nj < 4; nj++) {
            const int row0 = bm + wm + mi * 16 + (lane >> 2);
            const int c0 = bn + wn + nj * 8 + (lane & 3) * 2;
            if (c0 >= Nout) continue;
            const float b0 = bias[c0], b1 = bias[c0 + 1];
#pragma unroll
            for (int h = 0; h < 2; h++) {
                const int r = row0 + h * 8;
                float v0 = acc[mi][nj][h * 2 + 0] + b0;
                float v1 = acc[mi][nj][h * 2 + 1] + b1;
                if (mode == 0) {
                    // scalar stores: traj_all base offset is odd
                    C[(size_t)r * Nout + c0] = v0;
                    C[(size_t)r * Nout + c0 + 1] = v1;
                } else {
                    v0 = gelu_exact(v0);
                    v1 = gelu_exact(v1);
                    unsigned hp;
                    asm("cvt.rn.bf16x2.f32 %0, %1, %2;"
                        : "=r"(hp) : "f"(v1), "f"(v0));
                    const float f0 = __uint_as_float(hp << 16);
                    const float f1 = __uint_as_float(hp & 0xffff0000u);
                    unsigned lp;
                    asm("cvt.rn.bf16x2.f32 %0, %1, %2;"
                        : "=r"(lp) : "f"(v1 - f1), "f"(v0 - f0));
                    *reinterpret_cast<unsigned*>(Oh + (size_t)r * Nout + c0) = hp;
                    *reinterpret_cast<unsigned*>(Ol + (size_t)r * Nout + c0) = lp;
                }
            }
        }
    }
}

// ---------------------------------------------------------------------------
// Router final layer: logits[N,5] = (hi+lo)[N,128] @ W[128,5] + b[5]
// ---------------------------------------------------------------------------
__global__ __launch_bounds__(256)
void router_final(const __nv_bfloat16* __restrict__ hh,
                  const __nv_bfloat16* __restrict__ ll,
                  const float* __restrict__ W, const float* __restrict__ b,
                  float* __restrict__ logits) {
    __shared__ float ws[640];
    const int tid = threadIdx.x;
    for (int i = tid; i < 640; i += 256) ws[i] = W[i];
    __syncthreads();
    const int lane = tid & 31;
    const int tok = blockIdx.x * 8 + (tid >> 5);

    const size_t base = (size_t)tok * 128 + lane * 4;
    union { uint2 u; __nv_bfloat16 b[4]; } vh, vl;
    vh.u = *reinterpret_cast<const uint2*>(hh + base);
    vl.u = *reinterpret_cast<const uint2*>(ll + base);

    float p[5] = {0, 0, 0, 0, 0};
#pragma unroll
    for (int k = 0; k < 4; k++) {
        const float x = __bfloat162float(vh.b[k]) + __bfloat162float(vl.b[k]);
        const int kk = lane * 4 + k;
#pragma unroll
        for (int e = 0; e < 5; e++) p[e] = fmaf(x, ws[kk * 5 + e], p[e]);
    }
#pragma unroll
    for (int off = 16; off > 0; off >>= 1)
#pragma unroll
        for (int e = 0; e < 5; e++)
            p[e] += __shfl_down_sync(0xffffffffu, p[e], off);
    if (lane == 0) {
#pragma unroll
        for (int e = 0; e < 5; e++) logits[(size_t)tok * 5 + e] = p[e] + b[e];
    }
}

// ---------------------------------------------------------------------------
// Merged score-final (z=0 -> final_score, z>=1 -> score_all[z-1])
// ---------------------------------------------------------------------------
__global__ __launch_bounds__(256)
void score_final_all(const __nv_bfloat16* __restrict__ Ah0,
                     const __nv_bfloat16* __restrict__ Al0,
                     float* __restrict__ out) {
    const int z = blockIdx.y;
    const __nv_bfloat16* hh = Ah0 + (size_t)z * N_TOK * 64;
    const __nv_bfloat16* ll = Al0 + (size_t)z * N_TOK * 64;
    const float* W = g_barena + BO_WSF + z * 64;
    const float bconst = g_barena[BO_BSF + z];
    float* dst = (z == 0) ? (out + OFF_FINAL_SCORE)
                          : (out + OFF_SCORE_ALL + (size_t)(z - 1) * N_TOK);

    const int tid = threadIdx.x;
    const int lane = tid & 31;
    const int tok = blockIdx.x * 8 + (tid >> 5);
    const size_t base = (size_t)tok * 64 + lane * 2;
    union { unsigned u; __nv_bfloat16 b[2]; } vh, vl;
    vh.u = *reinterpret_cast<const unsigned*>(hh + base);
    vl.u = *reinterpret_cast<const unsigned*>(ll + base);
    float p = (__bfloat162float(vh.b[0]) + __bfloat162float(vl.b[0])) * W[lane * 2]
            + (__bfloat162float(vh.b[1]) + __bfloat162float(vl.b[1])) * W[lane * 2 + 1];
#pragma unroll
    for (int off = 16; off > 0; off >>= 1)
        p += __shfl_down_sync(0xffffffffu, p, off);
    if (lane == 0) dst[tok] = p + bconst;
}

// ---------------------------------------------------------------------------
// Aux-loss
// ---------------------------------------------------------------------------
__global__ void aux_accum(const float* __restrict__ logits, float* __restrict__ part) {
    __shared__ float red[256];
    const int tok = blockIdx.x * 256 + threadIdx.x;
    float l[5];
#pragma unroll
    for (int e = 0; e < 5; e++) l[e] = logits[(size_t)tok * 5 + e];
    float mx = l[0];
#pragma unroll
    for (int e = 1; e < 5; e++) mx = fmaxf(mx, l[e]);
    float p[5], s = 0.0f;
#pragma unroll
    for (int e = 0; e < 5; e++) { p[e] = expf(l[e] - mx); s += p[e]; }
    const float inv = 1.0f / s;
#pragma unroll
    for (int e = 0; e < 5; e++) {
        red[threadIdx.x] = p[e] * inv;
        __syncthreads();
        for (int off = 128; off > 0; off >>= 1) {
            if (threadIdx.x < off) red[threadIdx.x] += red[threadIdx.x + off];
            __syncthreads();
        }
        if (threadIdx.x == 0) part[blockIdx.x * 5 + e] = red[0];
        __syncthreads();
    }
}

__global__ void aux_final(const float* __restrict__ part, float* __restrict__ aux) {
    float s[5] = {0, 0, 0, 0, 0};
    for (int b = 0; b < 192; b++)
#pragma unroll
        for (int e = 0; e < 5; e++) s[e] += part[b * 5 + e];
    float ent = 0.0f, l2 = 0.0f;
#pragma unroll
    for (int e = 0; e < 5; e++) {
        const float a = s[e] / (float)N_TOK;
        ent -= a * logf(a + 1e-8f);
        l2 += (a - 0.2f) * (a - 0.2f);
    }
    l2 *= 0.2f;
    aux[0] = -ent * 0.01f + 0.01f * l2;
}

// ---------------------------------------------------------------------------
// Finalize: top-2 (lowest-index tie-break), softmax-of-2, gather + blend.
// ---------------------------------------------------------------------------
__global__ void finalize_kernel(const float* __restrict__ logits,
                                float* __restrict__ final_traj,
                                float* __restrict__ final_score,
                                float* __restrict__ topk_out,
                                const float* __restrict__ traj_all,
                                const float* __restrict__ score_all) {
    const int tok = blockIdx.x * 4 + (threadIdx.x >> 5);
    const int lane = threadIdx.x & 31;
    if (tok >= N_TOK) return;

    float l[5];
#pragma unroll
    for (int e = 0; e < 5; e++) l[e] = logits[(size_t)tok * 5 + e];

    int i0 = 0; float v0 = l[0];
#pragma unroll
    for (int e = 1; e < 5; e++)
        if (l[e] > v0) { v0 = l[e]; i0 = e; }
    int i1 = -1; float v1 = -3.4e38f;
#pragma unroll
    for (int e = 0; e < 5; e++)
        if (e != i0 && l[e] > v1) { v1 = l[e]; i1 = e; }

    const float e1 = expf(v1 - v0);
    const float inv = 1.0f / (1.0f + e1);
    const float p0 = inv, p1 = e1 * inv;

    if (lane == 0) {
        topk_out[(size_t)tok * 2 + 0] = (float)i0;
        topk_out[(size_t)tok * 2 + 1] = (float)i1;
        const float sh = final_score[tok];
        const float uns = p0 * score_all[(size_t)i0 * N_TOK + tok]
                        + p1 * score_all[(size_t)i1 * N_TOK + tok];
        final_score[tok] = 0.3f * sh + 0.7f * uns;
    }

    const float* t0 = traj_all + (size_t)i0 * N_TOK * 120 + (size_t)tok * 120;
    const float* t1 = traj_all + (size_t)i1 * N_TOK * 120 + (size_t)tok * 120;
    float* ft = final_traj + (size_t)tok * 120;
    for (int t = lane; t < 120; t += 32) {
        const float uns = p0 * t0[t] + p1 * t1[t];
        ft[t] = 0.3f * ft[t] + 0.7f * uns;
    }
}

// ---------------------------------------------------------------------------
// Host launcher
// ---------------------------------------------------------------------------
extern "C" void kernel_launch(void* const* d_in, const int* in_sizes, int n_in,
                              void* d_out, int out_size) {
    (void)in_sizes; (void)n_in; (void)out_size;

    cudaFuncSetAttribute(tc_gemm<128, 128, 136>,
                         cudaFuncAttributeMaxDynamicSharedMemorySize, 75776);
    cudaFuncSetAttribute(tc_gemm<256, 64, 72>,
                         cudaFuncAttributeMaxDynamicSharedMemorySize, 100352);

    __nv_bfloat16 *wh, *wl, *xh, *xl;
    __nv_bfloat16 *a1wh, *a1wl, *a1nh, *a1nl, *a2wh, *a2wl, *a2rh, *a2rl, *a2nh, *a2nl;
    float *barena, *part;
    cudaGetSymbolAddress((void**)&wh, g_wh);
    cudaGetSymbolAddress((void**)&wl, g_wl);
    cudaGetSymbolAddress((void**)&xh, g_xh);
    cudaGetSymbolAddress((void**)&xl, g_xl);
    cudaGetSymbolAddress((void**)&a1wh, g_a1wh);
    cudaGetSymbolAddress((void**)&a1wl, g_a1wl);
    cudaGetSymbolAddress((void**)&a1nh, g_a1nh);
    cudaGetSymbolAddress((void**)&a1nl, g_a1nl);
    cudaGetSymbolAddress((void**)&a2wh, g_a2wh);
    cudaGetSymbolAddress((void**)&a2wl, g_a2wl);
    cudaGetSymbolAddress((void**)&a2rh, g_a2rh);
    cudaGetSymbolAddress((void**)&a2rl, g_a2rl);
    cudaGetSymbolAddress((void**)&a2nh, g_a2nh);
    cudaGetSymbolAddress((void**)&a2nl, g_a2nl);
    cudaGetSymbolAddress((void**)&barena, g_barena);
    cudaGetSymbolAddress((void**)&part, g_part);

    const float* in[31];
    for (int i = 0; i < 31; i++) in[i] = (const float*)d_in[i];
    float* out = (float*)d_out;

    auto G128 = [&](const __nv_bfloat16* Ah_, const __nv_bfloat16* Al_,
                    long long a_zstr, int lda, int woff, long long w_zstr,
                    int b_off, int b_zstr, int Kd, int Nout, int nz, int mode,
                    float* C, __nv_bfloat16* Oh_, __nv_bfloat16* Ol_,
                    long long o_zstr) {
        dim3 grid((Nout + 127) / 128, N_TOK / 128, nz);
        tc_gemm<128, 128, 136><<<grid, 256, 75776>>>(
            Ah_, Al_, a_zstr, lda, wh + woff, wl + woff, w_zstr,
            b_off, b_zstr, Kd, Nout, mode, C, Oh_, Ol_, o_zstr);
    };

    const long long ZW = (long long)N_TOK * 256;
    const long long ZN = (long long)N_TOK * 128;
    const long long ZS = (long long)N_TOK * 64;

    // Slot 0: X split
    split_kernel<<<(N_TOK * 128 / 4 + 255) / 256, 256>>>(in[0], xh, xl,
                                                         N_TOK * 128 / 4);
    // Slot 1: ALL weight splits (contiguous arena dst)
    splitw_all<<<(246784 + 255) / 256, 256>>>(
        in[1], in[7], in[19],      // L1W: rw1, sh_tw1, ex_tw1
        in[13], in[25],            // L1N: sh_sw1, ex_sw1
        in[9], in[21],             // L2W: sh_tw2, ex_tw2
        in[3],                     // L2R: rw2
        in[15], in[27],            // L2N: sh_sw2, ex_sw2
        in[11], in[23],            // L3T: sh_tw3, ex_tw3
        wh, wl);
    // Slot 2: param gather
    gather_params<<<1, 256>>>(barena,
        in[2], in[8], in[20], in[14], in[26], in[10], in[22], in[4],
        in[16], in[28], in[12], in[24], in[17], in[29], in[18], in[30]);

    // Slot 3 (profiled): L1-wide (router, sh traj, 5 expert traj)
    G128(xh, xl, 0, 128, WO_L1W, 32768, BO_L1W, 256, 128, 256, 7, 1,
         nullptr, a1wh, a1wl, ZW);

    // L1-narrow (sh score, 5 expert score)
    G128(xh, xl, 0, 128, WO_L1N, 16384, BO_L1N, 128, 128, 128, 6, 1,
         nullptr, a1nh, a1nl, ZN);

    // L2-wide (sh traj L2, 5 expert traj L2)
    G128(a1wh + ZW, a1wl + ZW, ZW, 256, WO_L2W, 65536, BO_L2W, 256, 256, 256,
         6, 1, nullptr, a2wh, a2wl, ZW);

    // L2-router
    G128(a1wh, a1wl, 0, 256, WO_L2R, 0, BO_L2R, 0, 256, 128, 1, 1,
         nullptr, a2rh, a2rl, 0);

    // L2-narrow (Nout=64): 256x64 tile variant
    {
        dim3 grid(1, N_TOK / 256, 6);
        tc_gemm<256, 64, 72><<<grid, 256, 100352>>>(
            a1nh, a1nl, ZN, 128, wh + WO_L2N, wl + WO_L2N, 8192,
            BO_L2N, 64, 128, 64, 1, nullptr, a2nh, a2nl, ZS);
    }

    // L3-traj (sh -> final_traj, experts -> traj_all)
    G128(a2wh, a2wl, ZW, 256, WO_L3T, 30720, BO_L3T, 120, 256, 120, 6, 0,
         out, (__nv_bfloat16*)out, (__nv_bfloat16*)out, 0);

    // Router head + aux
    router_final<<<N_TOK / 8, 256>>>(a2rh, a2rl, in[5], in[6],
                                     out + OFF_LOGITS);
    aux_accum<<<192, 256>>>(out + OFF_LOGITS, part);
    aux_final<<<1, 1>>>(part, out + OFF_AUX);

    // Merged score finals
    {
        dim3 grid(N_TOK / 8, 6);
        score_final_all<<<grid, 256>>>(a2nh, a2nl, out);
    }

    // Top-2 combine + blend
    finalize_kernel<<<N_TOK / 4, 128>>>(out + OFF_LOGITS,
                                        out + OFF_FINAL_TRAJ,
                                        out + OFF_FINAL_SCORE,
                                        out + OFF_TOPK,
                                        out + OFF_TRAJ_ALL,
                                        out + OFF_SCORE_ALL);
}